// round 1
// baseline (speedup 1.0000x reference)
#include <cuda_runtime.h>

#define S_LEN 4096
#define HID   2048
#define NH    8
#define DHD   256

// Scratch (static device globals: allocation-free per harness rules)
__device__ float g_q[S_LEN * HID];     // 32 MB
__device__ float g_k[S_LEN * DHD];     //  4 MB
__device__ float g_v[S_LEN * DHD];     //  4 MB
__device__ float g_attn[S_LEN * HID];  // 32 MB

// ---------------------------------------------------------------------------
// SGEMM: C[M,N] = A[M,K] @ B[K,N], all row-major. 64x64 tile, 4x4 microtile.
// Requires M%64==0, N%64==0, K%16==0 (true for all shapes here).
// ---------------------------------------------------------------------------
__global__ __launch_bounds__(256) void sgemm64(
    const float* __restrict__ A, const float* __restrict__ B,
    float* __restrict__ C, int M, int N, int K)
{
    __shared__ float As[16][68];   // As[k][m], pad for bank spread + f4 align
    __shared__ float Bs[16][68];   // Bs[k][n]

    const int tid = threadIdx.x;
    const int tx  = tid & 15;      // col group
    const int ty  = tid >> 4;      // row group
    const int m0  = blockIdx.y * 64;
    const int n0  = blockIdx.x * 64;
    const int ldn = tid & 63;
    const int ldk = tid >> 6;

    float acc[4][4];
    #pragma unroll
    for (int i = 0; i < 4; ++i)
        #pragma unroll
        for (int j = 0; j < 4; ++j) acc[i][j] = 0.f;

    for (int k0 = 0; k0 < K; k0 += 16) {
        #pragma unroll
        for (int p = 0; p < 4; ++p) {
            int m = ty + p * 16;
            As[tx][m] = A[(size_t)(m0 + m) * K + k0 + tx];
        }
        #pragma unroll
        for (int p = 0; p < 4; ++p) {
            int kk = ldk + p * 4;
            Bs[kk][ldn] = B[(size_t)(k0 + kk) * N + n0 + ldn];
        }
        __syncthreads();
        #pragma unroll
        for (int k = 0; k < 16; ++k) {
            float4 a4 = *(const float4*)&As[k][ty * 4];
            float4 b4 = *(const float4*)&Bs[k][tx * 4];
            float av[4] = {a4.x, a4.y, a4.z, a4.w};
            float bv[4] = {b4.x, b4.y, b4.z, b4.w};
            #pragma unroll
            for (int i = 0; i < 4; ++i)
                #pragma unroll
                for (int j = 0; j < 4; ++j)
                    acc[i][j] += av[i] * bv[j];
        }
        __syncthreads();
    }
    #pragma unroll
    for (int i = 0; i < 4; ++i) {
        float4 o = make_float4(acc[i][0], acc[i][1], acc[i][2], acc[i][3]);
        *(float4*)&C[(size_t)(m0 + ty * 4 + i) * N + n0 + tx * 4] = o;
    }
}

// ---------------------------------------------------------------------------
// RoPE, in-place on Q [S, NH*DHD] and K [S, DHD]. Matches reference fp32 math:
// inv_freq = 1 / 10000^(j/128); out1 = x1*cos - x2*sin; out2 = x2*cos + x1*sin
// ---------------------------------------------------------------------------
__global__ void rope_kernel(float* __restrict__ q, float* __restrict__ k,
                            const int* __restrict__ pos_ids)
{
    const int s = blockIdx.x;
    const int j = threadIdx.x;  // 0..127
    const float p   = (float)pos_ids[s];
    const float inv = 1.0f / powf(10000.0f, (float)j * (1.0f / 128.0f));
    const float ang = p * inv;
    float sn, cs;
    sincosf(ang, &sn, &cs);

    #pragma unroll
    for (int h = 0; h < NH; ++h) {
        float* base = q + (size_t)s * HID + h * DHD;
        float x1 = base[j], x2 = base[j + 128];
        base[j]       = x1 * cs - x2 * sn;
        base[j + 128] = x2 * cs + x1 * sn;
    }
    float* kb = k + (size_t)s * DHD;
    float x1 = kb[j], x2 = kb[j + 128];
    kb[j]       = x1 * cs - x2 * sn;
    kb[j + 128] = x2 * cs + x1 * sn;
}

// ---------------------------------------------------------------------------
// Causal flash attention, fp32. One CTA = (head, 64-query tile).
// Q/K stored k-major in smem (stride 68), V row-major, P tile padded.
// acc layout per thread: row r4 = tid/4, dims d = g*64 + [0..63], g = tid%4.
// ---------------------------------------------------------------------------
#define QK_STRIDE 68
#define FA_SMEM ((2 * 256 * QK_STRIDE + 64 * 256 + 64 * QK_STRIDE) * 4)

__global__ __launch_bounds__(256, 1) void flash_kernel(
    const float* __restrict__ Qg, const float* __restrict__ Kg,
    const float* __restrict__ Vg, float* __restrict__ Og)
{
    extern __shared__ float sm[];
    float* Qts = sm;                         // [256][68]  (k-major)
    float* Kts = Qts + 256 * QK_STRIDE;      // [256][68]  (k-major)
    float* Vs  = Kts + 256 * QK_STRIDE;      // [64][256]
    float* Ps  = Vs  + 64 * 256;             // [64][68]

    const int tid = threadIdx.x;
    const int h   = blockIdx.y;
    const int it  = gridDim.x - 1 - blockIdx.x;  // longest rows launch first
    const int txa = tid & 15, tya = tid >> 4;    // phase-A 16x16 thread grid
    const int r4  = tid >> 2, g   = tid & 3;     // phase-B/C row mapping

    // Load Q tile transposed (once per CTA)
    const float* Qb = Qg + (size_t)(it * 64) * HID + h * DHD;
    for (int idx = tid; idx < 64 * 64; idx += 256) {
        int r = idx >> 6, c4 = idx & 63;
        float4 v = *(const float4*)&Qb[(size_t)r * HID + c4 * 4];
        Qts[(c4 * 4 + 0) * QK_STRIDE + r] = v.x;
        Qts[(c4 * 4 + 1) * QK_STRIDE + r] = v.y;
        Qts[(c4 * 4 + 2) * QK_STRIDE + r] = v.z;
        Qts[(c4 * 4 + 3) * QK_STRIDE + r] = v.w;
    }

    float acc[64];
    #pragma unroll
    for (int c = 0; c < 64; ++c) acc[c] = 0.f;
    float m_i = -1e30f, l_i = 0.f;

    for (int jt = 0; jt <= it; ++jt) {
        __syncthreads();  // protect Kts/Vs/Ps from prior-iter readers; covers Qts on iter 0
        const float* Kb = Kg + (size_t)(jt * 64) * DHD;
        const float* Vb = Vg + (size_t)(jt * 64) * DHD;
        for (int idx = tid; idx < 64 * 64; idx += 256) {
            int r = idx >> 6, c4 = idx & 63;
            float4 kv = *(const float4*)&Kb[(size_t)r * DHD + c4 * 4];
            Kts[(c4 * 4 + 0) * QK_STRIDE + r] = kv.x;
            Kts[(c4 * 4 + 1) * QK_STRIDE + r] = kv.y;
            Kts[(c4 * 4 + 2) * QK_STRIDE + r] = kv.z;
            Kts[(c4 * 4 + 3) * QK_STRIDE + r] = kv.w;
            *(float4*)&Vs[r * 256 + c4 * 4] = *(const float4*)&Vb[(size_t)r * DHD + c4 * 4];
        }
        __syncthreads();

        // ---- Phase A: S = (Q K^T) / 16 ----
        float s4[4][4];
        #pragma unroll
        for (int i = 0; i < 4; ++i)
            #pragma unroll
            for (int jj = 0; jj < 4; ++jj) s4[i][jj] = 0.f;

        #pragma unroll 8
        for (int k = 0; k < 256; ++k) {
            float4 a4 = *(const float4*)&Qts[k * QK_STRIDE + tya * 4];
            float4 b4 = *(const float4*)&Kts[k * QK_STRIDE + txa * 4];
            float av[4] = {a4.x, a4.y, a4.z, a4.w};
            float bv[4] = {b4.x, b4.y, b4.z, b4.w};
            #pragma unroll
            for (int i = 0; i < 4; ++i)
                #pragma unroll
                for (int jj = 0; jj < 4; ++jj)
                    s4[i][jj] += av[i] * bv[jj];
        }

        const bool diag = (jt == it);
        #pragma unroll
        for (int i = 0; i < 4; ++i) {
            int qr = tya * 4 + i;
            float v[4];
            #pragma unroll
            for (int jj = 0; jj < 4; ++jj) {
                float val = s4[i][jj] * 0.0625f;
                if (diag && (txa * 4 + jj) > qr) val = -1e30f;
                v[jj] = val;
            }
            *(float4*)&Ps[qr * QK_STRIDE + txa * 4] = make_float4(v[0], v[1], v[2], v[3]);
        }
        __syncthreads();

        // ---- Phase B: online softmax (4 threads per row) ----
        float mx = -1e30f;
        #pragma unroll
        for (int c = 0; c < 16; ++c)
            mx = fmaxf(mx, Ps[r4 * QK_STRIDE + g * 16 + c]);
        mx = fmaxf(mx, __shfl_xor_sync(0xffffffffu, mx, 1));
        mx = fmaxf(mx, __shfl_xor_sync(0xffffffffu, mx, 2));
        float m_new = fmaxf(m_i, mx);
        float corr  = __expf(m_i - m_new);
        float lsum  = 0.f;
        #pragma unroll
        for (int c = 0; c < 16; ++c) {
            float pv = __expf(Ps[r4 * QK_STRIDE + g * 16 + c] - m_new);
            Ps[r4 * QK_STRIDE + g * 16 + c] = pv;
            lsum += pv;
        }
        lsum += __shfl_xor_sync(0xffffffffu, lsum, 1);
        lsum += __shfl_xor_sync(0xffffffffu, lsum, 2);
        l_i = l_i * corr + lsum;
        m_i = m_new;
        #pragma unroll
        for (int c = 0; c < 64; ++c) acc[c] *= corr;
        __syncthreads();

        // ---- Phase C: acc += P @ V  (thread covers dims g*64 .. g*64+63) ----
        for (int kk = 0; kk < 64; ++kk) {
            float pv = Ps[r4 * QK_STRIDE + kk];
            const float4* vrow = (const float4*)&Vs[kk * 256 + g * 64];
            #pragma unroll
            for (int c4 = 0; c4 < 16; ++c4) {
                float4 vv = vrow[c4];
                acc[c4 * 4 + 0] += pv * vv.x;
                acc[c4 * 4 + 1] += pv * vv.y;
                acc[c4 * 4 + 2] += pv * vv.z;
                acc[c4 * 4 + 3] += pv * vv.w;
            }
        }
    }

    const float invl = 1.0f / l_i;
    float* Ob = Og + (size_t)(it * 64 + r4) * HID + h * DHD + g * 64;
    #pragma unroll
    for (int c4 = 0; c4 < 16; ++c4) {
        float4 o = make_float4(acc[c4 * 4 + 0] * invl, acc[c4 * 4 + 1] * invl,
                               acc[c4 * 4 + 2] * invl, acc[c4 * 4 + 3] * invl);
        *(float4*)&Ob[c4 * 4] = o;
    }
}

// ---------------------------------------------------------------------------
extern "C" void kernel_launch(void* const* d_in, const int* in_sizes, int n_in,
                              void* d_out, int out_size)
{
    const float* X   = (const float*)d_in[0];
    const int*   pos = (const int*)  d_in[1];
    const float* wq  = (const float*)d_in[2];
    const float* wk  = (const float*)d_in[3];
    const float* wv  = (const float*)d_in[4];
    const float* wo  = (const float*)d_in[5];
    float* out = (float*)d_out;

    float *q, *k, *v, *attn;
    cudaGetSymbolAddress((void**)&q,    g_q);
    cudaGetSymbolAddress((void**)&k,    g_k);
    cudaGetSymbolAddress((void**)&v,    g_v);
    cudaGetSymbolAddress((void**)&attn, g_attn);

    sgemm64<<<dim3(HID / 64, S_LEN / 64), 256>>>(X, wq, q, S_LEN, HID, HID);
    sgemm64<<<dim3(DHD / 64, S_LEN / 64), 256>>>(X, wk, k, S_LEN, DHD, HID);
    sgemm64<<<dim3(DHD / 64, S_LEN / 64), 256>>>(X, wv, v, S_LEN, DHD, HID);
    rope_kernel<<<S_LEN, 128>>>(q, k, pos);

    cudaFuncSetAttribute(flash_kernel,
                         cudaFuncAttributeMaxDynamicSharedMemorySize, FA_SMEM);
    flash_kernel<<<dim3(S_LEN / 64, NH), 256, FA_SMEM>>>(q, k, v, attn);

    sgemm64<<<dim3(HID / 64, S_LEN / 64), 256>>>(attn, wo, out, S_LEN, HID, HID);
}

// round 3
// speedup vs baseline: 1.6972x; 1.6972x over previous
#include <cuda_runtime.h>
#include <cstdint>

#define S_LEN 4096
#define HID   2048
#define NH    8
#define DHD   256

// ---------------------------------------------------------------------------
// Scratch (static device globals: allocation-free per harness rules)
// ---------------------------------------------------------------------------
__device__ float g_q[S_LEN * HID];       // 32 MB
__device__ float g_k[S_LEN * DHD];       //  4 MB
__device__ float g_v[S_LEN * DHD];       //  4 MB
__device__ float g_attn[S_LEN * HID];    // 32 MB
__device__ float g_wqT[HID * HID];       // 16 MB  [N=2048][K=2048]
__device__ float g_wkT[DHD * HID];       //  2 MB  [N=256 ][K=2048]
__device__ float g_wvT[DHD * HID];       //  2 MB
__device__ float g_woT[HID * HID];       // 16 MB

// ---------------------------------------------------------------------------
// tf32 helpers
// ---------------------------------------------------------------------------
__device__ __forceinline__ float tf32_rna(float x) {
    uint32_t h;
    asm("cvt.rna.tf32.f32 %0, %1;" : "=r"(h) : "f"(x));
    return __uint_as_float(h);
}
__device__ __forceinline__ void split4(float4 v, float4& hi, float4& lo) {
    hi.x = tf32_rna(v.x); lo.x = tf32_rna(v.x - hi.x);
    hi.y = tf32_rna(v.y); lo.y = tf32_rna(v.y - hi.y);
    hi.z = tf32_rna(v.z); lo.z = tf32_rna(v.z - hi.z);
    hi.w = tf32_rna(v.w); lo.w = tf32_rna(v.w - hi.w);
}

#define MMA_TF32(c, a, b)                                                   \
    asm volatile("mma.sync.aligned.m16n8k8.row.col.f32.tf32.tf32.f32 "      \
        "{%0,%1,%2,%3}, {%4,%5,%6,%7}, {%8,%9}, {%0,%1,%2,%3};"             \
        : "+f"((c)[0]), "+f"((c)[1]), "+f"((c)[2]), "+f"((c)[3])            \
        : "r"((a)[0]), "r"((a)[1]), "r"((a)[2]), "r"((a)[3]),               \
          "r"((b)[0]), "r"((b)[1]))

// ---------------------------------------------------------------------------
// 3xTF32 mma.sync GEMM: C[M,N] = A[M,K] @ Bt[N,K]^T, row-major fp32 in/out.
// CTA tile 128x128, 256 threads (8 warps, each 64x32), K-chunk 32.
// smem rows padded to 36 floats -> fragment LDS bank = (4g+tig)%32: conflict-free.
// ---------------------------------------------------------------------------
#define GEMM_SMEM (4 * 128 * 36 * 4)   // Ah, Al, Bh, Bl = 73728 B

__global__ __launch_bounds__(256, 1)
void gemm_mma_tf32x3(const float* __restrict__ A, const float* __restrict__ Bt,
                     float* __restrict__ C, int M, int N, int K)
{
    extern __shared__ float sm[];
    float (*Ah)[36] = (float(*)[36])(sm);
    float (*Al)[36] = (float(*)[36])(sm + 128 * 36);
    float (*Bh)[36] = (float(*)[36])(sm + 2 * 128 * 36);
    float (*Bl)[36] = (float(*)[36])(sm + 3 * 128 * 36);

    const int tid  = threadIdx.x;
    const int wid  = tid >> 5, lane = tid & 31;
    const int g    = lane >> 2, tig = lane & 3;
    const int wm   = (wid & 1) * 64;       // warp row offset (2 warp-rows)
    const int wn   = (wid >> 1) * 32;      // warp col offset (4 warp-cols)
    const int m0   = blockIdx.y * 128, n0 = blockIdx.x * 128;

    // gmem loader: thread covers one 128-row, 16-float half-chunk
    const int lr = tid >> 1;               // 0..127
    const int lc = (tid & 1) * 16;         // 0 or 16
    const float* Ag = A  + (size_t)(m0 + lr) * K + lc;
    const float* Bg = Bt + (size_t)(n0 + lr) * K + lc;

    float c[16][4];
    #pragma unroll
    for (int i = 0; i < 16; ++i)
        #pragma unroll
        for (int j = 0; j < 4; ++j) c[i][j] = 0.f;

    // prefetch chunk 0
    float4 pa[4], pb[4];
    #pragma unroll
    for (int j = 0; j < 4; ++j) {
        pa[j] = *(const float4*)(Ag + 4 * j);
        pb[j] = *(const float4*)(Bg + 4 * j);
    }

    for (int c0 = 0; c0 < K; c0 += 32) {
        // stage prefetched chunk into smem (tf32 hi/lo split)
        #pragma unroll
        for (int j = 0; j < 4; ++j) {
            float4 h, l;
            split4(pa[j], h, l);
            *(float4*)&Ah[lr][lc + 4 * j] = h;
            *(float4*)&Al[lr][lc + 4 * j] = l;
            split4(pb[j], h, l);
            *(float4*)&Bh[lr][lc + 4 * j] = h;
            *(float4*)&Bl[lr][lc + 4 * j] = l;
        }
        __syncthreads();

        // prefetch next chunk (overlaps with mma below)
        if (c0 + 32 < K) {
            #pragma unroll
            for (int j = 0; j < 4; ++j) {
                pa[j] = *(const float4*)(Ag + c0 + 32 + 4 * j);
                pb[j] = *(const float4*)(Bg + c0 + 32 + 4 * j);
            }
        }

        // compute: 4 k-steps of 8
        #pragma unroll
        for (int ks = 0; ks < 32; ks += 8) {
            uint32_t ah[4][4], al[4][4], bh[4][2], bl[4][2];
            #pragma unroll
            for (int mt = 0; mt < 4; ++mt) {
                const int r = wm + mt * 16;
                ah[mt][0] = __float_as_uint(Ah[r + g    ][ks + tig    ]);
                ah[mt][1] = __float_as_uint(Ah[r + g + 8][ks + tig    ]);
                ah[mt][2] = __float_as_uint(Ah[r + g    ][ks + tig + 4]);
                ah[mt][3] = __float_as_uint(Ah[r + g + 8][ks + tig + 4]);
                al[mt][0] = __float_as_uint(Al[r + g    ][ks + tig    ]);
                al[mt][1] = __float_as_uint(Al[r + g + 8][ks + tig    ]);
                al[mt][2] = __float_as_uint(Al[r + g    ][ks + tig + 4]);
                al[mt][3] = __float_as_uint(Al[r + g + 8][ks + tig + 4]);
            }
            #pragma unroll
            for (int nt = 0; nt < 4; ++nt) {
                const int r = wn + nt * 8 + g;
                bh[nt][0] = __float_as_uint(Bh[r][ks + tig    ]);
                bh[nt][1] = __float_as_uint(Bh[r][ks + tig + 4]);
                bl[nt][0] = __float_as_uint(Bl[r][ks + tig    ]);
                bl[nt][1] = __float_as_uint(Bl[r][ks + tig + 4]);
            }
            #pragma unroll
            for (int mt = 0; mt < 4; ++mt)
                #pragma unroll
                for (int nt = 0; nt < 4; ++nt) {
                    float* cc = c[mt * 4 + nt];
                    MMA_TF32(cc, ah[mt], bh[nt]);   // hi*hi
                    MMA_TF32(cc, ah[mt], bl[nt]);   // hi*lo
                    MMA_TF32(cc, al[mt], bh[nt]);   // lo*hi
                }
        }
        __syncthreads();
    }

    // epilogue: c0,c1 -> (row g, cols 2tig..2tig+1); c2,c3 -> row g+8
    #pragma unroll
    for (int mt = 0; mt < 4; ++mt)
        #pragma unroll
        for (int nt = 0; nt < 4; ++nt) {
            const float* cc = c[mt * 4 + nt];
            const int row = m0 + wm + mt * 16 + g;
            const int col = n0 + wn + nt * 8 + 2 * tig;
            *(float2*)&C[(size_t)row * N + col]       = make_float2(cc[0], cc[1]);
            *(float2*)&C[(size_t)(row + 8) * N + col] = make_float2(cc[2], cc[3]);
        }
}

// ---------------------------------------------------------------------------
// Tiled transpose: out[c][r] = in[r][c].  in: [R, C] row-major.
// ---------------------------------------------------------------------------
__global__ void transpose_kernel(const float* __restrict__ in, float* __restrict__ out,
                                 int R, int C)
{
    __shared__ float t[32][33];
    const int cx = blockIdx.x * 32 + threadIdx.x;
    #pragma unroll
    for (int j = 0; j < 4; ++j) {
        int r = blockIdx.y * 32 + threadIdx.y + j * 8;
        t[threadIdx.y + j * 8][threadIdx.x] = in[(size_t)r * C + cx];
    }
    __syncthreads();
    const int rr = blockIdx.y * 32 + threadIdx.x;
    #pragma unroll
    for (int j = 0; j < 4; ++j) {
        int cc = blockIdx.x * 32 + threadIdx.y + j * 8;
        out[(size_t)cc * R + rr] = t[threadIdx.x][threadIdx.y + j * 8];
    }
}

// ---------------------------------------------------------------------------
// RoPE, in-place on Q [S, NH*DHD] and K [S, DHD]
// ---------------------------------------------------------------------------
__global__ void rope_kernel(float* __restrict__ q, float* __restrict__ k,
                            const int* __restrict__ pos_ids)
{
    const int s = blockIdx.x;
    const int j = threadIdx.x;  // 0..127
    const float p   = (float)pos_ids[s];
    const float inv = 1.0f / powf(10000.0f, (float)j * (1.0f / 128.0f));
    float sn, cs;
    sincosf(p * inv, &sn, &cs);

    #pragma unroll
    for (int h = 0; h < NH; ++h) {
        float* base = q + (size_t)s * HID + h * DHD;
        float x1 = base[j], x2 = base[j + 128];
        base[j]       = x1 * cs - x2 * sn;
        base[j + 128] = x2 * cs + x1 * sn;
    }
    float* kb = k + (size_t)s * DHD;
    float x1 = kb[j], x2 = kb[j + 128];
    kb[j]       = x1 * cs - x2 * sn;
    kb[j + 128] = x2 * cs + x1 * sn;
}

// ---------------------------------------------------------------------------
// Causal flash attention, fp32 SIMT (unchanged; R4 target for mma.sync)
// ---------------------------------------------------------------------------
#define QK_STRIDE 68
#define FA_SMEM ((2 * 256 * QK_STRIDE + 64 * 256 + 64 * QK_STRIDE) * 4)

__global__ __launch_bounds__(256, 1) void flash_kernel(
    const float* __restrict__ Qg, const float* __restrict__ Kg,
    const float* __restrict__ Vg, float* __restrict__ Og)
{
    extern __shared__ float sm[];
    float* Qts = sm;                         // [256][68]  (k-major)
    float* Kts = Qts + 256 * QK_STRIDE;      // [256][68]  (k-major)
    float* Vs  = Kts + 256 * QK_STRIDE;      // [64][256]
    float* Ps  = Vs  + 64 * 256;             // [64][68]

    const int tid = threadIdx.x;
    const int h   = blockIdx.y;
    const int it  = gridDim.x - 1 - blockIdx.x;
    const int txa = tid & 15, tya = tid >> 4;
    const int r4  = tid >> 2, g   = tid & 3;

    const float* Qb = Qg + (size_t)(it * 64) * HID + h * DHD;
    for (int idx = tid; idx < 64 * 64; idx += 256) {
        int r = idx >> 6, c4 = idx & 63;
        float4 v = *(const float4*)&Qb[(size_t)r * HID + c4 * 4];
        Qts[(c4 * 4 + 0) * QK_STRIDE + r] = v.x;
        Qts[(c4 * 4 + 1) * QK_STRIDE + r] = v.y;
        Qts[(c4 * 4 + 2) * QK_STRIDE + r] = v.z;
        Qts[(c4 * 4 + 3) * QK_STRIDE + r] = v.w;
    }

    float acc[64];
    #pragma unroll
    for (int c = 0; c < 64; ++c) acc[c] = 0.f;
    float m_i = -1e30f, l_i = 0.f;

    for (int jt = 0; jt <= it; ++jt) {
        __syncthreads();
        const float* Kb = Kg + (size_t)(jt * 64) * DHD;
        const float* Vb = Vg + (size_t)(jt * 64) * DHD;
        for (int idx = tid; idx < 64 * 64; idx += 256) {
            int r = idx >> 6, c4 = idx & 63;
            float4 kv = *(const float4*)&Kb[(size_t)r * DHD + c4 * 4];
            Kts[(c4 * 4 + 0) * QK_STRIDE + r] = kv.x;
            Kts[(c4 * 4 + 1) * QK_STRIDE + r] = kv.y;
            Kts[(c4 * 4 + 2) * QK_STRIDE + r] = kv.z;
            Kts[(c4 * 4 + 3) * QK_STRIDE + r] = kv.w;
            *(float4*)&Vs[r * 256 + c4 * 4] = *(const float4*)&Vb[(size_t)r * DHD + c4 * 4];
        }
        __syncthreads();

        float s4[4][4];
        #pragma unroll
        for (int i = 0; i < 4; ++i)
            #pragma unroll
            for (int jj = 0; jj < 4; ++jj) s4[i][jj] = 0.f;

        #pragma unroll 8
        for (int k = 0; k < 256; ++k) {
            float4 a4 = *(const float4*)&Qts[k * QK_STRIDE + tya * 4];
            float4 b4 = *(const float4*)&Kts[k * QK_STRIDE + txa * 4];
            float av[4] = {a4.x, a4.y, a4.z, a4.w};
            float bv[4] = {b4.x, b4.y, b4.z, b4.w};
            #pragma unroll
            for (int i = 0; i < 4; ++i)
                #pragma unroll
                for (int jj = 0; jj < 4; ++jj)
                    s4[i][jj] += av[i] * bv[jj];
        }

        const bool diag = (jt == it);
        #pragma unroll
        for (int i = 0; i < 4; ++i) {
            int qr = tya * 4 + i;
            float v[4];
            #pragma unroll
            for (int jj = 0; jj < 4; ++jj) {
                float val = s4[i][jj] * 0.0625f;
                if (diag && (txa * 4 + jj) > qr) val = -1e30f;
                v[jj] = val;
            }
            *(float4*)&Ps[qr * QK_STRIDE + txa * 4] = make_float4(v[0], v[1], v[2], v[3]);
        }
        __syncthreads();

        float mx = -1e30f;
        #pragma unroll
        for (int c = 0; c < 16; ++c)
            mx = fmaxf(mx, Ps[r4 * QK_STRIDE + g * 16 + c]);
        mx = fmaxf(mx, __shfl_xor_sync(0xffffffffu, mx, 1));
        mx = fmaxf(mx, __shfl_xor_sync(0xffffffffu, mx, 2));
        float m_new = fmaxf(m_i, mx);
        float corr  = __expf(m_i - m_new);
        float lsum  = 0.f;
        #pragma unroll
        for (int c = 0; c < 16; ++c) {
            float pv = __expf(Ps[r4 * QK_STRIDE + g * 16 + c] - m_new);
            Ps[r4 * QK_STRIDE + g * 16 + c] = pv;
            lsum += pv;
        }
        lsum += __shfl_xor_sync(0xffffffffu, lsum, 1);
        lsum += __shfl_xor_sync(0xffffffffu, lsum, 2);
        l_i = l_i * corr + lsum;
        m_i = m_new;
        #pragma unroll
        for (int c = 0; c < 64; ++c) acc[c] *= corr;
        __syncthreads();

        #pragma unroll 4
        for (int kk = 0; kk < 64; ++kk) {
            float pv = Ps[r4 * QK_STRIDE + kk];
            const float4* vrow = (const float4*)&Vs[kk * 256 + g * 64];
            #pragma unroll
            for (int c4 = 0; c4 < 16; ++c4) {
                float4 vv = vrow[c4];
                acc[c4 * 4 + 0] += pv * vv.x;
                acc[c4 * 4 + 1] += pv * vv.y;
                acc[c4 * 4 + 2] += pv * vv.z;
                acc[c4 * 4 + 3] += pv * vv.w;
            }
        }
    }

    const float invl = 1.0f / l_i;
    float* Ob = Og + (size_t)(it * 64 + r4) * HID + h * DHD + g * 64;
    #pragma unroll
    for (int c4 = 0; c4 < 16; ++c4) {
        float4 o = make_float4(acc[c4 * 4 + 0] * invl, acc[c4 * 4 + 1] * invl,
                               acc[c4 * 4 + 2] * invl, acc[c4 * 4 + 3] * invl);
        *(float4*)&Ob[c4 * 4] = o;
    }
}

// ---------------------------------------------------------------------------
extern "C" void kernel_launch(void* const* d_in, const int* in_sizes, int n_in,
                              void* d_out, int out_size)
{
    const float* X   = (const float*)d_in[0];
    const int*   pos = (const int*)  d_in[1];
    const float* wq  = (const float*)d_in[2];
    const float* wk  = (const float*)d_in[3];
    const float* wv  = (const float*)d_in[4];
    const float* wo  = (const float*)d_in[5];
    float* out = (float*)d_out;

    float *q, *k, *v, *attn, *wqT, *wkT, *wvT, *woT;
    cudaGetSymbolAddress((void**)&q,    g_q);
    cudaGetSymbolAddress((void**)&k,    g_k);
    cudaGetSymbolAddress((void**)&v,    g_v);
    cudaGetSymbolAddress((void**)&attn, g_attn);
    cudaGetSymbolAddress((void**)&wqT,  g_wqT);
    cudaGetSymbolAddress((void**)&wkT,  g_wkT);
    cudaGetSymbolAddress((void**)&wvT,  g_wvT);
    cudaGetSymbolAddress((void**)&woT,  g_woT);

    // Weight transposes -> K-major [N, K]  (~30 us total)
    dim3 tb(32, 8);
    transpose_kernel<<<dim3(HID / 32, HID / 32), tb>>>(wq, wqT, HID, HID);
    transpose_kernel<<<dim3(DHD / 32, HID / 32), tb>>>(wk, wkT, HID, DHD);
    transpose_kernel<<<dim3(DHD / 32, HID / 32), tb>>>(wv, wvT, HID, DHD);
    transpose_kernel<<<dim3(HID / 32, HID / 32), tb>>>(wo, woT, HID, HID);

    cudaFuncSetAttribute(gemm_mma_tf32x3,
                         cudaFuncAttributeMaxDynamicSharedMemorySize, GEMM_SMEM);

    // QKV projections (mma.sync 3xTF32)
    gemm_mma_tf32x3<<<dim3(HID / 128, S_LEN / 128), 256, GEMM_SMEM>>>(X, wqT, q, S_LEN, HID, HID);
    gemm_mma_tf32x3<<<dim3(DHD / 128, S_LEN / 128), 256, GEMM_SMEM>>>(X, wkT, k, S_LEN, DHD, HID);
    gemm_mma_tf32x3<<<dim3(DHD / 128, S_LEN / 128), 256, GEMM_SMEM>>>(X, wvT, v, S_LEN, DHD, HID);

    rope_kernel<<<S_LEN, 128>>>(q, k, pos);

    cudaFuncSetAttribute(flash_kernel,
                         cudaFuncAttributeMaxDynamicSharedMemorySize, FA_SMEM);
    flash_kernel<<<dim3(S_LEN / 64, NH), 256, FA_SMEM>>>(q, k, v, attn);

    // Output projection
    gemm_mma_tf32x3<<<dim3(HID / 128, S_LEN / 128), 256, GEMM_SMEM>>>(attn, woT, out, S_LEN, HID, HID);
}

// round 4
// speedup vs baseline: 4.8138x; 2.8363x over previous
#include <cuda_runtime.h>
#include <cstdint>

#define S_LEN 4096
#define HID   2048
#define NH    8
#define DHD   256

// ---------------------------------------------------------------------------
// Scratch (static device globals: allocation-free per harness rules)
// ---------------------------------------------------------------------------
__device__ float g_q[S_LEN * HID];       // 32 MB
__device__ float g_k[S_LEN * DHD];       //  4 MB
__device__ float g_v[S_LEN * DHD];       //  4 MB
__device__ float g_attn[S_LEN * HID];    // 32 MB
__device__ float g_wqT[HID * HID];       // 16 MB  [N=2048][K=2048]
__device__ float g_wkT[DHD * HID];       //  2 MB
__device__ float g_wvT[DHD * HID];       //  2 MB
__device__ float g_woT[HID * HID];       // 16 MB

// ---------------------------------------------------------------------------
// tf32 helpers
// ---------------------------------------------------------------------------
__device__ __forceinline__ float tf32_rna(float x) {
    uint32_t h;
    asm("cvt.rna.tf32.f32 %0, %1;" : "=r"(h) : "f"(x));
    return __uint_as_float(h);
}
__device__ __forceinline__ void split1(float x, uint32_t& hi, uint32_t& lo) {
    float h = tf32_rna(x);
    hi = __float_as_uint(h);
    lo = __float_as_uint(tf32_rna(x - h));
}
__device__ __forceinline__ void split4(float4 v, float4& hi, float4& lo) {
    hi.x = tf32_rna(v.x); lo.x = tf32_rna(v.x - hi.x);
    hi.y = tf32_rna(v.y); lo.y = tf32_rna(v.y - hi.y);
    hi.z = tf32_rna(v.z); lo.z = tf32_rna(v.z - hi.z);
    hi.w = tf32_rna(v.w); lo.w = tf32_rna(v.w - hi.w);
}

#define MMA_TF32(c, a, b)                                                   \
    asm volatile("mma.sync.aligned.m16n8k8.row.col.f32.tf32.tf32.f32 "      \
        "{%0,%1,%2,%3}, {%4,%5,%6,%7}, {%8,%9}, {%0,%1,%2,%3};"             \
        : "+f"((c)[0]), "+f"((c)[1]), "+f"((c)[2]), "+f"((c)[3])            \
        : "r"((a)[0]), "r"((a)[1]), "r"((a)[2]), "r"((a)[3]),               \
          "r"((b)[0]), "r"((b)[1]))

// ---------------------------------------------------------------------------
// 3xTF32 mma.sync GEMM: C[M,N] = A[M,K] @ Bt[N,K]^T (unchanged from R3)
// ---------------------------------------------------------------------------
#define GEMM_SMEM (4 * 128 * 36 * 4)

__global__ __launch_bounds__(256, 1)
void gemm_mma_tf32x3(const float* __restrict__ A, const float* __restrict__ Bt,
                     float* __restrict__ C, int M, int N, int K)
{
    extern __shared__ float sm[];
    float (*Ah)[36] = (float(*)[36])(sm);
    float (*Al)[36] = (float(*)[36])(sm + 128 * 36);
    float (*Bh)[36] = (float(*)[36])(sm + 2 * 128 * 36);
    float (*Bl)[36] = (float(*)[36])(sm + 3 * 128 * 36);

    const int tid  = threadIdx.x;
    const int wid  = tid >> 5, lane = tid & 31;
    const int g    = lane >> 2, tig = lane & 3;
    const int wm   = (wid & 1) * 64;
    const int wn   = (wid >> 1) * 32;
    const int m0   = blockIdx.y * 128, n0 = blockIdx.x * 128;

    const int lr = tid >> 1;
    const int lc = (tid & 1) * 16;
    const float* Ag = A  + (size_t)(m0 + lr) * K + lc;
    const float* Bg = Bt + (size_t)(n0 + lr) * K + lc;

    float c[16][4];
    #pragma unroll
    for (int i = 0; i < 16; ++i)
        #pragma unroll
        for (int j = 0; j < 4; ++j) c[i][j] = 0.f;

    float4 pa[4], pb[4];
    #pragma unroll
    for (int j = 0; j < 4; ++j) {
        pa[j] = *(const float4*)(Ag + 4 * j);
        pb[j] = *(const float4*)(Bg + 4 * j);
    }

    for (int c0 = 0; c0 < K; c0 += 32) {
        #pragma unroll
        for (int j = 0; j < 4; ++j) {
            float4 h, l;
            split4(pa[j], h, l);
            *(float4*)&Ah[lr][lc + 4 * j] = h;
            *(float4*)&Al[lr][lc + 4 * j] = l;
            split4(pb[j], h, l);
            *(float4*)&Bh[lr][lc + 4 * j] = h;
            *(float4*)&Bl[lr][lc + 4 * j] = l;
        }
        __syncthreads();

        if (c0 + 32 < K) {
            #pragma unroll
            for (int j = 0; j < 4; ++j) {
                pa[j] = *(const float4*)(Ag + c0 + 32 + 4 * j);
                pb[j] = *(const float4*)(Bg + c0 + 32 + 4 * j);
            }
        }

        #pragma unroll
        for (int ks = 0; ks < 32; ks += 8) {
            uint32_t ah[4][4], al[4][4], bh[4][2], bl[4][2];
            #pragma unroll
            for (int mt = 0; mt < 4; ++mt) {
                const int r = wm + mt * 16;
                ah[mt][0] = __float_as_uint(Ah[r + g    ][ks + tig    ]);
                ah[mt][1] = __float_as_uint(Ah[r + g + 8][ks + tig    ]);
                ah[mt][2] = __float_as_uint(Ah[r + g    ][ks + tig + 4]);
                ah[mt][3] = __float_as_uint(Ah[r + g + 8][ks + tig + 4]);
                al[mt][0] = __float_as_uint(Al[r + g    ][ks + tig    ]);
                al[mt][1] = __float_as_uint(Al[r + g + 8][ks + tig    ]);
                al[mt][2] = __float_as_uint(Al[r + g    ][ks + tig + 4]);
                al[mt][3] = __float_as_uint(Al[r + g + 8][ks + tig + 4]);
            }
            #pragma unroll
            for (int nt = 0; nt < 4; ++nt) {
                const int r = wn + nt * 8 + g;
                bh[nt][0] = __float_as_uint(Bh[r][ks + tig    ]);
                bh[nt][1] = __float_as_uint(Bh[r][ks + tig + 4]);
                bl[nt][0] = __float_as_uint(Bl[r][ks + tig    ]);
                bl[nt][1] = __float_as_uint(Bl[r][ks + tig + 4]);
            }
            #pragma unroll
            for (int mt = 0; mt < 4; ++mt)
                #pragma unroll
                for (int nt = 0; nt < 4; ++nt) {
                    float* cc = c[mt * 4 + nt];
                    MMA_TF32(cc, ah[mt], bh[nt]);
                    MMA_TF32(cc, ah[mt], bl[nt]);
                    MMA_TF32(cc, al[mt], bh[nt]);
                }
        }
        __syncthreads();
    }

    #pragma unroll
    for (int mt = 0; mt < 4; ++mt)
        #pragma unroll
        for (int nt = 0; nt < 4; ++nt) {
            const float* cc = c[mt * 4 + nt];
            const int row = m0 + wm + mt * 16 + g;
            const int col = n0 + wn + nt * 8 + 2 * tig;
            *(float2*)&C[(size_t)row * N + col]       = make_float2(cc[0], cc[1]);
            *(float2*)&C[(size_t)(row + 8) * N + col] = make_float2(cc[2], cc[3]);
        }
}

// ---------------------------------------------------------------------------
// Tiled transpose
// ---------------------------------------------------------------------------
__global__ void transpose_kernel(const float* __restrict__ in, float* __restrict__ out,
                                 int R, int C)
{
    __shared__ float t[32][33];
    const int cx = blockIdx.x * 32 + threadIdx.x;
    #pragma unroll
    for (int j = 0; j < 4; ++j) {
        int r = blockIdx.y * 32 + threadIdx.y + j * 8;
        t[threadIdx.y + j * 8][threadIdx.x] = in[(size_t)r * C + cx];
    }
    __syncthreads();
    const int rr = blockIdx.y * 32 + threadIdx.x;
    #pragma unroll
    for (int j = 0; j < 4; ++j) {
        int cc = blockIdx.x * 32 + threadIdx.y + j * 8;
        out[(size_t)cc * R + rr] = t[threadIdx.x][threadIdx.y + j * 8];
    }
}

// ---------------------------------------------------------------------------
// RoPE, in-place on Q and K
// ---------------------------------------------------------------------------
__global__ void rope_kernel(float* __restrict__ q, float* __restrict__ k,
                            const int* __restrict__ pos_ids)
{
    const int s = blockIdx.x;
    const int j = threadIdx.x;
    const float p   = (float)pos_ids[s];
    const float inv = 1.0f / powf(10000.0f, (float)j * (1.0f / 128.0f));
    float sn, cs;
    sincosf(p * inv, &sn, &cs);

    #pragma unroll
    for (int h = 0; h < NH; ++h) {
        float* base = q + (size_t)s * HID + h * DHD;
        float x1 = base[j], x2 = base[j + 128];
        base[j]       = x1 * cs - x2 * sn;
        base[j + 128] = x2 * cs + x1 * sn;
    }
    float* kb = k + (size_t)s * DHD;
    float x1 = kb[j], x2 = kb[j + 128];
    kb[j]       = x1 * cs - x2 * sn;
    kb[j + 128] = x2 * cs + x1 * sn;
}

// ---------------------------------------------------------------------------
// Flash attention with mma.sync tf32x3 for both QK^T and P*V.
// CTA = (64-row q tile, head). KV tile 64. 256 threads (8 warps).
// smem: Q[64][260], K[64][260], V[64][264], P[64][68], row state.
// ---------------------------------------------------------------------------
#define QPAD 260
#define VPAD 264
#define PPAD 68
#define FA2_FLOATS (64 * QPAD * 2 + 64 * VPAD + 64 * PPAD + 3 * 64)
#define FA2_SMEM   (FA2_FLOATS * 4)

__global__ __launch_bounds__(256, 1) void flash_mma_kernel(
    const float* __restrict__ Qg, const float* __restrict__ Kg,
    const float* __restrict__ Vg, float* __restrict__ Og)
{
    extern __shared__ float sm[];
    float (*Qs)[QPAD] = (float(*)[QPAD])(sm);
    float (*Ks)[QPAD] = (float(*)[QPAD])(sm + 64 * QPAD);
    float (*Vs)[VPAD] = (float(*)[VPAD])(sm + 2 * 64 * QPAD);
    float (*Ps)[PPAD] = (float(*)[PPAD])(sm + 2 * 64 * QPAD + 64 * VPAD);
    float* mrow = sm + 2 * 64 * QPAD + 64 * VPAD + 64 * PPAD;
    float* lrow = mrow + 64;
    float* crow = lrow + 64;

    const int tid  = threadIdx.x;
    const int wid  = tid >> 5, lane = tid & 31;
    const int g    = lane >> 2, tig = lane & 3;
    const int h    = blockIdx.y;
    const int it   = gridDim.x - 1 - blockIdx.x;   // longest rows first

    // QK^T warp mapping: 2 M-groups x 4 N-groups
    const int wqm = (wid & 1) * 32;
    const int wqn = (wid >> 1) * 16;
    // P*V warp mapping: 4 M-groups x 2 N-groups
    const int wpm = (wid & 3) * 16;
    const int wpn = (wid >> 2) * 128;

    // loader mapping: row = tid & 63, quarter = tid >> 6 (64 floats)
    const int lr = tid & 63, lq = (tid >> 6) * 64;

    // softmax mapping: 4 threads per row
    const int srow = tid >> 2, sseg = (tid & 3) * 16;

    // ---- load Q tile (once) + init row state ----
    {
        const float* Qb = Qg + (size_t)(it * 64 + lr) * HID + h * DHD + lq;
        #pragma unroll
        for (int i = 0; i < 16; ++i)
            *(float4*)&Qs[lr][lq + 4 * i] = *(const float4*)(Qb + 4 * i);
        if (tid < 64) { mrow[tid] = -1e30f; lrow[tid] = 0.f; }
    }

    float o[16][4];
    #pragma unroll
    for (int i = 0; i < 16; ++i)
        #pragma unroll
        for (int j = 0; j < 4; ++j) o[i][j] = 0.f;

    for (int jt = 0; jt <= it; ++jt) {
        __syncthreads();   // prior-iter readers of Ks/Vs/Ps done (covers Qs on iter 0)

        // ---- load K,V tiles ----
        {
            const float* Kb = Kg + (size_t)(jt * 64 + lr) * DHD + lq;
            const float* Vb = Vg + (size_t)(jt * 64 + lr) * DHD + lq;
            #pragma unroll
            for (int i = 0; i < 16; ++i) {
                *(float4*)&Ks[lr][lq + 4 * i] = *(const float4*)(Kb + 4 * i);
                *(float4*)&Vs[lr][lq + 4 * i] = *(const float4*)(Vb + 4 * i);
            }
        }
        __syncthreads();

        // ---- Phase A: S = Q K^T (raw, scaled later). 32 k-steps of 8. ----
        {
            float s[2][2][4];
            #pragma unroll
            for (int a = 0; a < 2; ++a)
                #pragma unroll
                for (int b = 0; b < 2; ++b)
                    #pragma unroll
                    for (int j = 0; j < 4; ++j) s[a][b][j] = 0.f;

            #pragma unroll 4
            for (int ks = 0; ks < 32; ++ks) {
                const int k0 = ks * 8;
                uint32_t ah[2][4], al[2][4], bh[2][2], bl[2][2];
                #pragma unroll
                for (int mf = 0; mf < 2; ++mf) {
                    const int r = wqm + mf * 16;
                    split1(Qs[r + g    ][k0 + tig    ], ah[mf][0], al[mf][0]);
                    split1(Qs[r + g + 8][k0 + tig    ], ah[mf][1], al[mf][1]);
                    split1(Qs[r + g    ][k0 + tig + 4], ah[mf][2], al[mf][2]);
                    split1(Qs[r + g + 8][k0 + tig + 4], ah[mf][3], al[mf][3]);
                }
                #pragma unroll
                for (int nf = 0; nf < 2; ++nf) {
                    const int r = wqn + nf * 8 + g;
                    split1(Ks[r][k0 + tig    ], bh[nf][0], bl[nf][0]);
                    split1(Ks[r][k0 + tig + 4], bh[nf][1], bl[nf][1]);
                }
                #pragma unroll
                for (int mf = 0; mf < 2; ++mf)
                    #pragma unroll
                    for (int nf = 0; nf < 2; ++nf) {
                        float* cc = s[mf][nf];
                        MMA_TF32(cc, ah[mf], bh[nf]);
                        MMA_TF32(cc, ah[mf], bl[nf]);
                        MMA_TF32(cc, al[mf], bh[nf]);
                    }
            }
            #pragma unroll
            for (int mf = 0; mf < 2; ++mf)
                #pragma unroll
                for (int nf = 0; nf < 2; ++nf) {
                    const int row = wqm + mf * 16 + g;
                    const int col = wqn + nf * 8 + 2 * tig;
                    *(float2*)&Ps[row][col]     = make_float2(s[mf][nf][0], s[mf][nf][1]);
                    *(float2*)&Ps[row + 8][col] = make_float2(s[mf][nf][2], s[mf][nf][3]);
                }
        }
        __syncthreads();

        // ---- Phase B: online softmax (scale 1/16, causal mask on diagonal) ----
        {
            const bool diag = (jt == it);
            float mx = -1e30f;
            #pragma unroll
            for (int c = 0; c < 16; ++c) {
                const int col = sseg + c;
                float val = Ps[srow][col] * 0.0625f;
                if (diag && col > srow) val = -1e30f;
                Ps[srow][col] = val;
                mx = fmaxf(mx, val);
            }
            mx = fmaxf(mx, __shfl_xor_sync(0xffffffffu, mx, 1));
            mx = fmaxf(mx, __shfl_xor_sync(0xffffffffu, mx, 2));
            const float m_old = mrow[srow];
            const float m_new = fmaxf(m_old, mx);
            const float corr  = __expf(m_old - m_new);
            float lsum = 0.f;
            #pragma unroll
            for (int c = 0; c < 16; ++c) {
                const int col = sseg + c;
                float pv = __expf(Ps[srow][col] - m_new);
                Ps[srow][col] = pv;
                lsum += pv;
            }
            lsum += __shfl_xor_sync(0xffffffffu, lsum, 1);
            lsum += __shfl_xor_sync(0xffffffffu, lsum, 2);
            if ((tid & 3) == 0) {
                mrow[srow] = m_new;
                lrow[srow] = lrow[srow] * corr + lsum;
                crow[srow] = corr;
            }
        }
        __syncthreads();

        // ---- Phase C: acc = acc*corr + P @ V. 8 k-steps of 8. ----
        {
            const float c_lo = crow[wpm + g];
            const float c_hi = crow[wpm + g + 8];
            #pragma unroll
            for (int nf = 0; nf < 16; ++nf) {
                o[nf][0] *= c_lo; o[nf][1] *= c_lo;
                o[nf][2] *= c_hi; o[nf][3] *= c_hi;
            }
            #pragma unroll
            for (int ks = 0; ks < 8; ++ks) {
                const int k0 = ks * 8;
                uint32_t ah[4], al[4];
                split1(Ps[wpm + g    ][k0 + tig    ], ah[0], al[0]);
                split1(Ps[wpm + g + 8][k0 + tig    ], ah[1], al[1]);
                split1(Ps[wpm + g    ][k0 + tig + 4], ah[2], al[2]);
                split1(Ps[wpm + g + 8][k0 + tig + 4], ah[3], al[3]);
                #pragma unroll
                for (int nf = 0; nf < 16; ++nf) {
                    const int cb = wpn + nf * 8 + g;
                    uint32_t bh[2], bl[2];
                    split1(Vs[k0 + tig    ][cb], bh[0], bl[0]);
                    split1(Vs[k0 + tig + 4][cb], bh[1], bl[1]);
                    float* cc = o[nf];
                    MMA_TF32(cc, ah, bh);
                    MMA_TF32(cc, ah, bl);
                    MMA_TF32(cc, al, bh);
                }
            }
        }
    }

    // ---- normalize and write out ----
    __syncthreads();
    {
        const float inv_lo = 1.0f / lrow[wpm + g];
        const float inv_hi = 1.0f / lrow[wpm + g + 8];
        const int row_lo = it * 64 + wpm + g;
        const int row_hi = row_lo + 8;
        #pragma unroll
        for (int nf = 0; nf < 16; ++nf) {
            const int col = h * DHD + wpn + nf * 8 + 2 * tig;
            *(float2*)&Og[(size_t)row_lo * HID + col] =
                make_float2(o[nf][0] * inv_lo, o[nf][1] * inv_lo);
            *(float2*)&Og[(size_t)row_hi * HID + col] =
                make_float2(o[nf][2] * inv_hi, o[nf][3] * inv_hi);
        }
    }
}

// ---------------------------------------------------------------------------
extern "C" void kernel_launch(void* const* d_in, const int* in_sizes, int n_in,
                              void* d_out, int out_size)
{
    const float* X   = (const float*)d_in[0];
    const int*   pos = (const int*)  d_in[1];
    const float* wq  = (const float*)d_in[2];
    const float* wk  = (const float*)d_in[3];
    const float* wv  = (const float*)d_in[4];
    const float* wo  = (const float*)d_in[5];
    float* out = (float*)d_out;

    float *q, *k, *v, *attn, *wqT, *wkT, *wvT, *woT;
    cudaGetSymbolAddress((void**)&q,    g_q);
    cudaGetSymbolAddress((void**)&k,    g_k);
    cudaGetSymbolAddress((void**)&v,    g_v);
    cudaGetSymbolAddress((void**)&attn, g_attn);
    cudaGetSymbolAddress((void**)&wqT,  g_wqT);
    cudaGetSymbolAddress((void**)&wkT,  g_wkT);
    cudaGetSymbolAddress((void**)&wvT,  g_wvT);
    cudaGetSymbolAddress((void**)&woT,  g_woT);

    dim3 tb(32, 8);
    transpose_kernel<<<dim3(HID / 32, HID / 32), tb>>>(wq, wqT, HID, HID);
    transpose_kernel<<<dim3(DHD / 32, HID / 32), tb>>>(wk, wkT, HID, DHD);
    transpose_kernel<<<dim3(DHD / 32, HID / 32), tb>>>(wv, wvT, HID, DHD);
    transpose_kernel<<<dim3(HID / 32, HID / 32), tb>>>(wo, woT, HID, HID);

    cudaFuncSetAttribute(gemm_mma_tf32x3,
                         cudaFuncAttributeMaxDynamicSharedMemorySize, GEMM_SMEM);

    gemm_mma_tf32x3<<<dim3(HID / 128, S_LEN / 128), 256, GEMM_SMEM>>>(X, wqT, q, S_LEN, HID, HID);
    gemm_mma_tf32x3<<<dim3(DHD / 128, S_LEN / 128), 256, GEMM_SMEM>>>(X, wkT, k, S_LEN, DHD, HID);
    gemm_mma_tf32x3<<<dim3(DHD / 128, S_LEN / 128), 256, GEMM_SMEM>>>(X, wvT, v, S_LEN, DHD, HID);

    rope_kernel<<<S_LEN, 128>>>(q, k, pos);

    cudaFuncSetAttribute(flash_mma_kernel,
                         cudaFuncAttributeMaxDynamicSharedMemorySize, FA2_SMEM);
    flash_mma_kernel<<<dim3(S_LEN / 64, NH), 256, FA2_SMEM>>>(q, k, v, attn);

    gemm_mma_tf32x3<<<dim3(HID / 128, S_LEN / 128), 256, GEMM_SMEM>>>(attn, woT, out, S_LEN, HID, HID);
}

// round 5
// speedup vs baseline: 8.6528x; 1.7975x over previous
#include <cuda_runtime.h>
#include <cuda_bf16.h>
#include <cstdint>

#define S_LEN 4096
#define HID   2048
#define NH    8
#define DHD   256

// ---------------------------------------------------------------------------
// Scratch (static device globals: allocation-free per harness rules)
// ---------------------------------------------------------------------------
__device__ float g_q[S_LEN * HID];       // 32 MB
__device__ float g_k[S_LEN * DHD];       //  4 MB
__device__ float g_v[S_LEN * DHD];       //  4 MB
__device__ float g_attn[S_LEN * HID];    // 32 MB
__device__ float g_wqT[HID * HID];       // 16 MB  [N=2048][K=2048]
__device__ float g_wkT[DHD * HID];       //  2 MB
__device__ float g_wvT[DHD * HID];       //  2 MB
__device__ float g_woT[HID * HID];       // 16 MB

// ---------------------------------------------------------------------------
// bf16 split helpers.  Packed word = {low16: element k, high16: element k+1}.
// ---------------------------------------------------------------------------
__device__ __forceinline__ float bf16_rn_f32(float x) {
    return __bfloat162float(__float2bfloat16(x));
}
__device__ __forceinline__ uint32_t bf16pack(float lo_k, float hi_k) {
    uint32_t r;
    asm("cvt.rn.bf16x2.f32 %0, %1, %2;" : "=r"(r) : "f"(hi_k), "f"(lo_k));
    return r;
}
// float4 (k..k+3) -> 2 hi words + 2 lo words
__device__ __forceinline__ void split_pack4(float4 v, uint32_t* h, uint32_t* l) {
    h[0] = bf16pack(v.x, v.y);
    h[1] = bf16pack(v.z, v.w);
    l[0] = bf16pack(v.x - bf16_rn_f32(v.x), v.y - bf16_rn_f32(v.y));
    l[1] = bf16pack(v.z - bf16_rn_f32(v.z), v.w - bf16_rn_f32(v.w));
}

#define MMA_BF16(c, a, b)                                                   \
    asm volatile("mma.sync.aligned.m16n8k16.row.col.f32.bf16.bf16.f32 "     \
        "{%0,%1,%2,%3}, {%4,%5,%6,%7}, {%8,%9}, {%0,%1,%2,%3};"             \
        : "+f"((c)[0]), "+f"((c)[1]), "+f"((c)[2]), "+f"((c)[3])            \
        : "r"((a)[0]), "r"((a)[1]), "r"((a)[2]), "r"((a)[3]),               \
          "r"((b)[0]), "r"((b)[1]))

// ---------------------------------------------------------------------------
// 3x-bf16 mma.sync GEMM: C[M,N] = A[M,K] @ Bt[N,K]^T, row-major fp32 in/out.
// CTA tile 128x128, 256 threads (8 warps x 64x32 warp tile), K-chunk 32.
// smem: packed-u32 arrays [128][20]  (pitch 20 -> fragment banks 20g+tig: CF)
// ---------------------------------------------------------------------------
#define GP 20
#define GEMM_SMEM (4 * 128 * GP * 4)   // 40960 B

__global__ __launch_bounds__(256, 1)
void gemm_mma_bf16x3(const float* __restrict__ A, const float* __restrict__ Bt,
                     float* __restrict__ C, int M, int N, int K)
{
    extern __shared__ uint32_t smu[];
    uint32_t* AH = smu;
    uint32_t* AL = smu + 128 * GP;
    uint32_t* BH = smu + 2 * 128 * GP;
    uint32_t* BL = smu + 3 * 128 * GP;

    const int tid  = threadIdx.x;
    const int wid  = tid >> 5, lane = tid & 31;
    const int g    = lane >> 2, tig = lane & 3;
    const int wm   = (wid & 1) * 64;
    const int wn   = (wid >> 1) * 32;
    const int m0   = blockIdx.y * 128, n0 = blockIdx.x * 128;

    const int lr = tid >> 1;               // 0..127
    const int lc = (tid & 1) * 16;         // float offset 0 or 16
    const int wb0 = lc >> 1;               // word offset 0 or 8
    const float* Ag = A  + (size_t)(m0 + lr) * K + lc;
    const float* Bg = Bt + (size_t)(n0 + lr) * K + lc;

    float c[16][4];
    #pragma unroll
    for (int i = 0; i < 16; ++i)
        #pragma unroll
        for (int j = 0; j < 4; ++j) c[i][j] = 0.f;

    float4 pa[4], pb[4];
    #pragma unroll
    for (int j = 0; j < 4; ++j) {
        pa[j] = *(const float4*)(Ag + 4 * j);
        pb[j] = *(const float4*)(Bg + 4 * j);
    }

    for (int c0 = 0; c0 < K; c0 += 32) {
        #pragma unroll
        for (int j = 0; j < 4; ++j) {
            uint32_t h[2], l[2];
            split_pack4(pa[j], h, l);
            AH[lr * GP + wb0 + 2 * j]     = h[0];
            AH[lr * GP + wb0 + 2 * j + 1] = h[1];
            AL[lr * GP + wb0 + 2 * j]     = l[0];
            AL[lr * GP + wb0 + 2 * j + 1] = l[1];
            split_pack4(pb[j], h, l);
            BH[lr * GP + wb0 + 2 * j]     = h[0];
            BH[lr * GP + wb0 + 2 * j + 1] = h[1];
            BL[lr * GP + wb0 + 2 * j]     = l[0];
            BL[lr * GP + wb0 + 2 * j + 1] = l[1];
        }
        __syncthreads();

        if (c0 + 32 < K) {
            #pragma unroll
            for (int j = 0; j < 4; ++j) {
                pa[j] = *(const float4*)(Ag + c0 + 32 + 4 * j);
                pb[j] = *(const float4*)(Bg + c0 + 32 + 4 * j);
            }
        }

        #pragma unroll
        for (int ks = 0; ks < 2; ++ks) {     // 2 k-steps of 16
            const int wb = ks * 8;
            uint32_t ah[4][4], al[4][4], bh[4][2], bl[4][2];
            #pragma unroll
            for (int mt = 0; mt < 4; ++mt) {
                const int r = wm + mt * 16;
                ah[mt][0] = AH[(r + g    ) * GP + wb + tig    ];
                ah[mt][1] = AH[(r + g + 8) * GP + wb + tig    ];
                ah[mt][2] = AH[(r + g    ) * GP + wb + tig + 4];
                ah[mt][3] = AH[(r + g + 8) * GP + wb + tig + 4];
                al[mt][0] = AL[(r + g    ) * GP + wb + tig    ];
                al[mt][1] = AL[(r + g + 8) * GP + wb + tig    ];
                al[mt][2] = AL[(r + g    ) * GP + wb + tig + 4];
                al[mt][3] = AL[(r + g + 8) * GP + wb + tig + 4];
            }
            #pragma unroll
            for (int nt = 0; nt < 4; ++nt) {
                const int r = wn + nt * 8 + g;
                bh[nt][0] = BH[r * GP + wb + tig    ];
                bh[nt][1] = BH[r * GP + wb + tig + 4];
                bl[nt][0] = BL[r * GP + wb + tig    ];
                bl[nt][1] = BL[r * GP + wb + tig + 4];
            }
            #pragma unroll
            for (int mt = 0; mt < 4; ++mt)
                #pragma unroll
                for (int nt = 0; nt < 4; ++nt) {
                    float* cc = c[mt * 4 + nt];
                    MMA_BF16(cc, ah[mt], bh[nt]);
                    MMA_BF16(cc, ah[mt], bl[nt]);
                    MMA_BF16(cc, al[mt], bh[nt]);
                }
        }
        __syncthreads();
    }

    #pragma unroll
    for (int mt = 0; mt < 4; ++mt)
        #pragma unroll
        for (int nt = 0; nt < 4; ++nt) {
            const float* cc = c[mt * 4 + nt];
            const int row = m0 + wm + mt * 16 + g;
            const int col = n0 + wn + nt * 8 + 2 * tig;
            *(float2*)&C[(size_t)row * N + col]       = make_float2(cc[0], cc[1]);
            *(float2*)&C[(size_t)(row + 8) * N + col] = make_float2(cc[2], cc[3]);
        }
}

// ---------------------------------------------------------------------------
// Tiled transpose
// ---------------------------------------------------------------------------
__global__ void transpose_kernel(const float* __restrict__ in, float* __restrict__ out,
                                 int R, int C)
{
    __shared__ float t[32][33];
    const int cx = blockIdx.x * 32 + threadIdx.x;
    #pragma unroll
    for (int j = 0; j < 4; ++j) {
        int r = blockIdx.y * 32 + threadIdx.y + j * 8;
        t[threadIdx.y + j * 8][threadIdx.x] = in[(size_t)r * C + cx];
    }
    __syncthreads();
    const int rr = blockIdx.y * 32 + threadIdx.x;
    #pragma unroll
    for (int j = 0; j < 4; ++j) {
        int cc = blockIdx.x * 32 + threadIdx.y + j * 8;
        out[(size_t)cc * R + rr] = t[threadIdx.x][threadIdx.y + j * 8];
    }
}

// ---------------------------------------------------------------------------
// RoPE, in-place on Q and K
// ---------------------------------------------------------------------------
__global__ void rope_kernel(float* __restrict__ q, float* __restrict__ k,
                            const int* __restrict__ pos_ids)
{
    const int s = blockIdx.x;
    const int j = threadIdx.x;
    const float p   = (float)pos_ids[s];
    const float inv = 1.0f / powf(10000.0f, (float)j * (1.0f / 128.0f));
    float sn, cs;
    sincosf(p * inv, &sn, &cs);

    #pragma unroll
    for (int h = 0; h < NH; ++h) {
        float* base = q + (size_t)s * HID + h * DHD;
        float x1 = base[j], x2 = base[j + 128];
        base[j]       = x1 * cs - x2 * sn;
        base[j + 128] = x2 * cs + x1 * sn;
    }
    float* kb = k + (size_t)s * DHD;
    float x1 = kb[j], x2 = kb[j + 128];
    kb[j]       = x1 * cs - x2 * sn;
    kb[j + 128] = x2 * cs + x1 * sn;
}

// ---------------------------------------------------------------------------
// Flash attention, mma.sync bf16x3 for QK^T and P*V.
// CTA = (64-row q tile, head), KV tile 64, 256 threads (8 warps).
// smem (u32 words):
//   QH/QL/KH/KL [64][132]  packed bf16x2 along k (pitch 132 % 32 == 4: CF)
//   VTH/VTL    [256][36]   V transposed: [dim][kv-pair], pitch 36 % 32 == 4
//   PS         [64][68]    fp32 scores; after softmax holds packed P:
//                          words 0..31 = Ph, words 32..63 = Pl
//   state: mrow/lrow/crow [64] each
// ---------------------------------------------------------------------------
#define QP 132
#define VP 36
#define PP 68
#define OFF_QH 0
#define OFF_QL (OFF_QH + 64 * QP)
#define OFF_KH (OFF_QL + 64 * QP)
#define OFF_KL (OFF_KH + 64 * QP)
#define OFF_VTH (OFF_KL + 64 * QP)
#define OFF_VTL (OFF_VTH + 256 * VP)
#define OFF_PS  (OFF_VTL + 256 * VP)
#define OFF_M   (OFF_PS + 64 * PP)
#define OFF_L   (OFF_M + 64)
#define OFF_C   (OFF_L + 64)
#define FA3_SMEM ((OFF_C + 64) * 4)

__global__ __launch_bounds__(256, 1) void flash_mma_bf16(
    const float* __restrict__ Qg, const float* __restrict__ Kg,
    const float* __restrict__ Vg, float* __restrict__ Og)
{
    extern __shared__ uint32_t smu[];
    float* smf = (float*)smu;

    const int tid  = threadIdx.x;
    const int wid  = tid >> 5, lane = tid & 31;
    const int g    = lane >> 2, tig = lane & 3;
    const int h    = blockIdx.y;
    const int it   = gridDim.x - 1 - blockIdx.x;   // longest rows first

    // QK^T warp mapping: 2 M-groups x 4 N-groups
    const int wqm = (wid & 1) * 32;
    const int wqn = (wid >> 1) * 16;
    // P*V warp mapping: 4 M-groups x 2 N-groups (128 dims each)
    const int wpm = (wid & 3) * 16;
    const int wpn = (wid >> 2) * 128;

    // Q/K loader: row = tid&63, quarter = (tid>>6)*64 floats
    const int lr = tid & 63, lq = (tid >> 6) * 64;
    // V loader: row-pair = tid>>3, 8 threads x 32 dims
    const int vrp = tid >> 3, vin = tid & 7;
    // softmax: 4 threads per row
    const int srow = tid >> 2, sseg = tig * 16;

    // ---- stage Q (packed bf16x2 hi/lo) + init state ----
    {
        const float* Qb = Qg + (size_t)(it * 64 + lr) * HID + h * DHD + lq;
        const int base = lr * QP + (lq >> 1);
        #pragma unroll
        for (int i = 0; i < 16; ++i) {
            uint32_t hw[2], lw[2];
            split_pack4(*(const float4*)(Qb + 4 * i), hw, lw);
            smu[OFF_QH + base + 2 * i]     = hw[0];
            smu[OFF_QH + base + 2 * i + 1] = hw[1];
            smu[OFF_QL + base + 2 * i]     = lw[0];
            smu[OFF_QL + base + 2 * i + 1] = lw[1];
        }
        if (tid < 64) { smf[OFF_M + tid] = -1e30f; smf[OFF_L + tid] = 0.f; }
    }

    float o[16][4];
    #pragma unroll
    for (int i = 0; i < 16; ++i)
        #pragma unroll
        for (int j = 0; j < 4; ++j) o[i][j] = 0.f;

    for (int jt = 0; jt <= it; ++jt) {
        __syncthreads();   // prior-iter readers done (covers Q staging on iter 0)

        // ---- stage K (packed along k) ----
        {
            const float* Kb = Kg + (size_t)(jt * 64 + lr) * DHD + lq;
            const int base = lr * QP + (lq >> 1);
            #pragma unroll
            for (int i = 0; i < 16; ++i) {
                uint32_t hw[2], lw[2];
                split_pack4(*(const float4*)(Kb + 4 * i), hw, lw);
                smu[OFF_KH + base + 2 * i]     = hw[0];
                smu[OFF_KH + base + 2 * i + 1] = hw[1];
                smu[OFF_KL + base + 2 * i]     = lw[0];
                smu[OFF_KL + base + 2 * i + 1] = lw[1];
            }
        }
        // ---- stage V transposed: VT[dim][rp] packs kv rows (2rp, 2rp+1) ----
        {
            const float* V0 = Vg + (size_t)(jt * 64 + 2 * vrp) * DHD;
            const float* V1 = V0 + DHD;
            #pragma unroll
            for (int i = 0; i < 8; ++i) {
                const int d = i * 32 + vin * 4;
                float4 a = *(const float4*)(V0 + d);
                float4 b = *(const float4*)(V1 + d);
                const float av[4] = {a.x, a.y, a.z, a.w};
                const float bv[4] = {b.x, b.y, b.z, b.w};
                #pragma unroll
                for (int j = 0; j < 4; ++j) {
                    smu[OFF_VTH + (d + j) * VP + vrp] = bf16pack(av[j], bv[j]);
                    smu[OFF_VTL + (d + j) * VP + vrp] =
                        bf16pack(av[j] - bf16_rn_f32(av[j]), bv[j] - bf16_rn_f32(bv[j]));
                }
            }
        }
        __syncthreads();

        // ---- Phase A: S = Q K^T  (16 k-steps of 16) ----
        {
            float s[2][2][4];
            #pragma unroll
            for (int a = 0; a < 2; ++a)
                #pragma unroll
                for (int b = 0; b < 2; ++b)
                    #pragma unroll
                    for (int j = 0; j < 4; ++j) s[a][b][j] = 0.f;

            #pragma unroll 4
            for (int ks = 0; ks < 16; ++ks) {
                const int wb = ks * 8;
                uint32_t ah[2][4], al[2][4], bh[2][2], bl[2][2];
                #pragma unroll
                for (int mf = 0; mf < 2; ++mf) {
                    const int r = wqm + mf * 16;
                    ah[mf][0] = smu[OFF_QH + (r + g    ) * QP + wb + tig    ];
                    ah[mf][1] = smu[OFF_QH + (r + g + 8) * QP + wb + tig    ];
                    ah[mf][2] = smu[OFF_QH + (r + g    ) * QP + wb + tig + 4];
                    ah[mf][3] = smu[OFF_QH + (r + g + 8) * QP + wb + tig + 4];
                    al[mf][0] = smu[OFF_QL + (r + g    ) * QP + wb + tig    ];
                    al[mf][1] = smu[OFF_QL + (r + g + 8) * QP + wb + tig    ];
                    al[mf][2] = smu[OFF_QL + (r + g    ) * QP + wb + tig + 4];
                    al[mf][3] = smu[OFF_QL + (r + g + 8) * QP + wb + tig + 4];
                }
                #pragma unroll
                for (int nf = 0; nf < 2; ++nf) {
                    const int r = wqn + nf * 8 + g;
                    bh[nf][0] = smu[OFF_KH + r * QP + wb + tig    ];
                    bh[nf][1] = smu[OFF_KH + r * QP + wb + tig + 4];
                    bl[nf][0] = smu[OFF_KL + r * QP + wb + tig    ];
                    bl[nf][1] = smu[OFF_KL + r * QP + wb + tig + 4];
                }
                #pragma unroll
                for (int mf = 0; mf < 2; ++mf)
                    #pragma unroll
                    for (int nf = 0; nf < 2; ++nf) {
                        float* cc = s[mf][nf];
                        MMA_BF16(cc, ah[mf], bh[nf]);
                        MMA_BF16(cc, ah[mf], bl[nf]);
                        MMA_BF16(cc, al[mf], bh[nf]);
                    }
            }
            #pragma unroll
            for (int mf = 0; mf < 2; ++mf)
                #pragma unroll
                for (int nf = 0; nf < 2; ++nf) {
                    const int row = wqm + mf * 16 + g;
                    const int col = wqn + nf * 8 + 2 * tig;
                    *(float2*)&smf[OFF_PS + row * PP + col] =
                        make_float2(s[mf][nf][0], s[mf][nf][1]);
                    *(float2*)&smf[OFF_PS + (row + 8) * PP + col] =
                        make_float2(s[mf][nf][2], s[mf][nf][3]);
                }
        }
        __syncthreads();

        // ---- Phase B: online softmax; pack P in-place (Ph w0-31, Pl w32-63) ----
        {
            const bool diag = (jt == it);
            float pv[16];
            float mx = -1e30f;
            #pragma unroll
            for (int c = 0; c < 16; ++c) {
                const int col = sseg + c;
                float val = smf[OFF_PS + srow * PP + col] * 0.0625f;
                if (diag && col > srow) val = -1e30f;
                pv[c] = val;
                mx = fmaxf(mx, val);
            }
            mx = fmaxf(mx, __shfl_xor_sync(0xffffffffu, mx, 1));
            mx = fmaxf(mx, __shfl_xor_sync(0xffffffffu, mx, 2));
            const float m_old = smf[OFF_M + srow];
            const float m_new = fmaxf(m_old, mx);
            const float corr  = __expf(m_old - m_new);
            float lsum = 0.f;
            #pragma unroll
            for (int c = 0; c < 16; ++c) {
                pv[c] = __expf(pv[c] - m_new);
                lsum += pv[c];
            }
            lsum += __shfl_xor_sync(0xffffffffu, lsum, 1);
            lsum += __shfl_xor_sync(0xffffffffu, lsum, 2);
            if (tig == 0) {
                smf[OFF_M + srow] = m_new;
                smf[OFF_L + srow] = smf[OFF_L + srow] * corr + lsum;
                smf[OFF_C + srow] = corr;
            }
            __syncwarp();   // all reads of this row's fp32 S done before overwrite
            const int wbase = OFF_PS + srow * PP + tig * 8;
            #pragma unroll
            for (int i = 0; i < 8; ++i) {
                const float a = pv[2 * i], b = pv[2 * i + 1];
                smu[wbase + i]      = bf16pack(a, b);
                smu[wbase + 32 + i] = bf16pack(a - bf16_rn_f32(a), b - bf16_rn_f32(b));
            }
        }
        __syncthreads();

        // ---- Phase C: acc = acc*corr + P @ V  (4 k-steps of 16) ----
        {
            const float c_lo = smf[OFF_C + wpm + g];
            const float c_hi = smf[OFF_C + wpm + g + 8];
            #pragma unroll
            for (int nf = 0; nf < 16; ++nf) {
                o[nf][0] *= c_lo; o[nf][1] *= c_lo;
                o[nf][2] *= c_hi; o[nf][3] *= c_hi;
            }
            #pragma unroll
            for (int ks = 0; ks < 4; ++ks) {
                const int wb = ks * 8;
                uint32_t ah[4], al[4];
                ah[0] = smu[OFF_PS + (wpm + g    ) * PP + wb + tig    ];
                ah[1] = smu[OFF_PS + (wpm + g + 8) * PP + wb + tig    ];
                ah[2] = smu[OFF_PS + (wpm + g    ) * PP + wb + tig + 4];
                ah[3] = smu[OFF_PS + (wpm + g + 8) * PP + wb + tig + 4];
                al[0] = smu[OFF_PS + (wpm + g    ) * PP + 32 + wb + tig    ];
                al[1] = smu[OFF_PS + (wpm + g + 8) * PP + 32 + wb + tig    ];
                al[2] = smu[OFF_PS + (wpm + g    ) * PP + 32 + wb + tig + 4];
                al[3] = smu[OFF_PS + (wpm + g + 8) * PP + 32 + wb + tig + 4];
                #pragma unroll
                for (int nf = 0; nf < 16; ++nf) {
                    const int cb = wpn + nf * 8 + g;
                    uint32_t bh[2], bl[2];
                    bh[0] = smu[OFF_VTH + cb * VP + wb + tig    ];
                    bh[1] = smu[OFF_VTH + cb * VP + wb + tig + 4];
                    bl[0] = smu[OFF_VTL + cb * VP + wb + tig    ];
                    bl[1] = smu[OFF_VTL + cb * VP + wb + tig + 4];
                    float* cc = o[nf];
                    MMA_BF16(cc, ah, bh);
                    MMA_BF16(cc, ah, bl);
                    MMA_BF16(cc, al, bh);
                }
            }
        }
    }

    // ---- normalize and write out ----
    __syncthreads();
    {
        const float inv_lo = 1.0f / smf[OFF_L + wpm + g];
        const float inv_hi = 1.0f / smf[OFF_L + wpm + g + 8];
        const int row_lo = it * 64 + wpm + g;
        const int row_hi = row_lo + 8;
        #pragma unroll
        for (int nf = 0; nf < 16; ++nf) {
            const int col = h * DHD + wpn + nf * 8 + 2 * tig;
            *(float2*)&Og[(size_t)row_lo * HID + col] =
                make_float2(o[nf][0] * inv_lo, o[nf][1] * inv_lo);
            *(float2*)&Og[(size_t)row_hi * HID + col] =
                make_float2(o[nf][2] * inv_hi, o[nf][3] * inv_hi);
        }
    }
}

// ---------------------------------------------------------------------------
extern "C" void kernel_launch(void* const* d_in, const int* in_sizes, int n_in,
                              void* d_out, int out_size)
{
    const float* X   = (const float*)d_in[0];
    const int*   pos = (const int*)  d_in[1];
    const float* wq  = (const float*)d_in[2];
    const float* wk  = (const float*)d_in[3];
    const float* wv  = (const float*)d_in[4];
    const float* wo  = (const float*)d_in[5];
    float* out = (float*)d_out;

    float *q, *k, *v, *attn, *wqT, *wkT, *wvT, *woT;
    cudaGetSymbolAddress((void**)&q,    g_q);
    cudaGetSymbolAddress((void**)&k,    g_k);
    cudaGetSymbolAddress((void**)&v,    g_v);
    cudaGetSymbolAddress((void**)&attn, g_attn);
    cudaGetSymbolAddress((void**)&wqT,  g_wqT);
    cudaGetSymbolAddress((void**)&wkT,  g_wkT);
    cudaGetSymbolAddress((void**)&wvT,  g_wvT);
    cudaGetSymbolAddress((void**)&woT,  g_woT);

    dim3 tb(32, 8);
    transpose_kernel<<<dim3(HID / 32, HID / 32), tb>>>(wq, wqT, HID, HID);
    transpose_kernel<<<dim3(DHD / 32, HID / 32), tb>>>(wk, wkT, HID, DHD);
    transpose_kernel<<<dim3(DHD / 32, HID / 32), tb>>>(wv, wvT, HID, DHD);
    transpose_kernel<<<dim3(HID / 32, HID / 32), tb>>>(wo, woT, HID, HID);

    cudaFuncSetAttribute(gemm_mma_bf16x3,
                         cudaFuncAttributeMaxDynamicSharedMemorySize, GEMM_SMEM);

    gemm_mma_bf16x3<<<dim3(HID / 128, S_LEN / 128), 256, GEMM_SMEM>>>(X, wqT, q, S_LEN, HID, HID);
    gemm_mma_bf16x3<<<dim3(DHD / 128, S_LEN / 128), 256, GEMM_SMEM>>>(X, wkT, k, S_LEN, DHD, HID);
    gemm_mma_bf16x3<<<dim3(DHD / 128, S_LEN / 128), 256, GEMM_SMEM>>>(X, wvT, v, S_LEN, DHD, HID);

    rope_kernel<<<S_LEN, 128>>>(q, k, pos);

    cudaFuncSetAttribute(flash_mma_bf16,
                         cudaFuncAttributeMaxDynamicSharedMemorySize, FA3_SMEM);
    flash_mma_bf16<<<dim3(S_LEN / 64, NH), 256, FA3_SMEM>>>(q, k, v, attn);

    gemm_mma_bf16x3<<<dim3(HID / 128, S_LEN / 128), 256, GEMM_SMEM>>>(attn, woT, out, S_LEN, HID, HID);
}

// round 6
// speedup vs baseline: 9.5176x; 1.0999x over previous
#include <cuda_runtime.h>
#include <cuda_bf16.h>
#include <cstdint>

#define S_LEN 4096
#define HID   2048
#define NH    8
#define DHD   256
#define KW    1024      // HID/2 words per row (packed bf16x2)
#define DKW   128       // DHD/2 words

// ---------------------------------------------------------------------------
// Scratch (static device globals: allocation-free per harness rules)
// ---------------------------------------------------------------------------
__device__ float    g_q[S_LEN * HID];
__device__ float    g_k[S_LEN * DHD];
__device__ float    g_v[S_LEN * DHD];
__device__ uint32_t g_xH[S_LEN * KW],  g_xL[S_LEN * KW];    // split X
__device__ uint32_t g_qH[S_LEN * KW],  g_qL[S_LEN * KW];    // split roped Q
__device__ uint32_t g_kH[S_LEN * DKW], g_kL[S_LEN * DKW];   // split roped K
__device__ uint32_t g_aH[S_LEN * KW],  g_aL[S_LEN * KW];    // split attn
__device__ uint32_t g_wqH[HID * KW],  g_wqL[HID * KW];      // [N][Kw] K-major
__device__ uint32_t g_wkH[DHD * KW],  g_wkL[DHD * KW];
__device__ uint32_t g_wvH[DHD * KW],  g_wvL[DHD * KW];
__device__ uint32_t g_woH[HID * KW],  g_woL[HID * KW];

// ---------------------------------------------------------------------------
// helpers
// ---------------------------------------------------------------------------
__device__ __forceinline__ uint32_t smem_u32(const void* p) {
    uint32_t a;
    asm("{ .reg .u64 t; cvta.to.shared.u64 t, %1; cvt.u32.u64 %0, t; }"
        : "=r"(a) : "l"(p));
    return a;
}
__device__ __forceinline__ float bf16_rn_f32(float x) {
    return __bfloat162float(__float2bfloat16(x));
}
__device__ __forceinline__ uint32_t bf16pack(float lo_k, float hi_k) {
    uint32_t r;
    asm("cvt.rn.bf16x2.f32 %0, %1, %2;" : "=r"(r) : "f"(hi_k), "f"(lo_k));
    return r;
}
__device__ __forceinline__ void packpair(float a, float b, uint32_t& H, uint32_t& L) {
    H = bf16pack(a, b);
    L = bf16pack(a - bf16_rn_f32(a), b - bf16_rn_f32(b));
}
__device__ __forceinline__ void split_pack4(float4 v, uint32_t* h, uint32_t* l) {
    packpair(v.x, v.y, h[0], l[0]);
    packpair(v.z, v.w, h[1], l[1]);
}
__device__ __forceinline__ void ldsm_x4(uint32_t* r, uint32_t addr) {
    asm volatile("ldmatrix.sync.aligned.m8n8.x4.shared.b16 {%0,%1,%2,%3}, [%4];"
        : "=r"(r[0]), "=r"(r[1]), "=r"(r[2]), "=r"(r[3]) : "r"(addr));
}
#define MMA_BF16(c, a, b)                                                   \
    asm volatile("mma.sync.aligned.m16n8k16.row.col.f32.bf16.bf16.f32 "     \
        "{%0,%1,%2,%3}, {%4,%5,%6,%7}, {%8,%9}, {%0,%1,%2,%3};"             \
        : "+f"((c)[0]), "+f"((c)[1]), "+f"((c)[2]), "+f"((c)[3])            \
        : "r"((a)[0]), "r"((a)[1]), "r"((a)[2]), "r"((a)[3]),               \
          "r"((b)[0]), "r"((b)[1]))
#define CP16(sm, gm) \
    asm volatile("cp.async.cg.shared.global [%0], [%1], 16;" :: "r"(sm), "l"(gm))
#define CPCOMMIT() asm volatile("cp.async.commit_group;")
#define CPWAIT0()  asm volatile("cp.async.wait_group 0;")
#define CPWAIT1()  asm volatile("cp.async.wait_group 1;")

// ---------------------------------------------------------------------------
// split_rows: fp32 [rows][2*Kw] -> packed hi/lo u32 [rows][Kw]
// thread handles 4 words (8 floats)
// ---------------------------------------------------------------------------
__global__ void split_rows(const float* __restrict__ in,
                           uint32_t* __restrict__ oH, uint32_t* __restrict__ oL)
{
    const size_t t = (size_t)blockIdx.x * blockDim.x + threadIdx.x;
    const float* p = in + t * 8;
    uint32_t h[2], l[2];
    split_pack4(*(const float4*)p, h, l);
    uint32_t h2[2], l2[2];
    split_pack4(*(const float4*)(p + 4), h2, l2);
    uint4 H = make_uint4(h[0], h[1], h2[0], h2[1]);
    uint4 L = make_uint4(l[0], l[1], l2[0], l2[1]);
    *(uint4*)&oH[t * 4] = H;
    *(uint4*)&oL[t * 4] = L;
}

// ---------------------------------------------------------------------------
// transpose_split: W [R=K][C=N] fp32 -> WT hi/lo u32 [N][R/2]
// ---------------------------------------------------------------------------
__global__ void transpose_split(const float* __restrict__ in,
                                uint32_t* __restrict__ oH, uint32_t* __restrict__ oL,
                                int R, int C)
{
    __shared__ float t[32][33];
    const int c0 = blockIdx.x * 32, r0 = blockIdx.y * 32;
    const int tx = threadIdx.x, ty = threadIdx.y;
    #pragma unroll
    for (int j = 0; j < 4; ++j)
        t[ty + 8 * j][tx] = in[(size_t)(r0 + ty + 8 * j) * C + c0 + tx];
    __syncthreads();
    const int Rw = R >> 1;
    #pragma unroll
    for (int j = 0; j < 2; ++j) {
        const int jj = ty + 8 * j;         // 0..15
        const float a = t[2 * jj][tx], b = t[2 * jj + 1][tx];
        uint32_t H, L;
        packpair(a, b, H, L);
        oH[(size_t)(c0 + tx) * Rw + (r0 >> 1) + jj] = H;
        oL[(size_t)(c0 + tx) * Rw + (r0 >> 1) + jj] = L;
    }
}

// ---------------------------------------------------------------------------
// rope_split: read fp32 q/k, apply RoPE, write packed hi/lo bf16 (pairs along dim)
// block = 64 threads (one per dim-pair), grid = S
// ---------------------------------------------------------------------------
__global__ void rope_split(const float* __restrict__ q, const float* __restrict__ k,
                           const int* __restrict__ pos,
                           uint32_t* __restrict__ qH, uint32_t* __restrict__ qL,
                           uint32_t* __restrict__ kH, uint32_t* __restrict__ kL)
{
    const int s = blockIdx.x;
    const int j = threadIdx.x;               // pair index 0..63
    const float p = (float)pos[s];
    const float ia = 1.0f / powf(10000.0f, (float)(2 * j)     * (1.0f / 128.0f));
    const float ib = 1.0f / powf(10000.0f, (float)(2 * j + 1) * (1.0f / 128.0f));
    float sa, ca, sb, cb;
    sincosf(p * ia, &sa, &ca);
    sincosf(p * ib, &sb, &cb);

    #pragma unroll
    for (int h = 0; h < NH; ++h) {
        const float* base = q + (size_t)s * HID + h * DHD;
        float2 x1 = *(const float2*)&base[2 * j];
        float2 x2 = *(const float2*)&base[128 + 2 * j];
        const float o1a = x1.x * ca - x2.x * sa;
        const float o1b = x1.y * cb - x2.y * sb;
        const float o2a = x2.x * ca + x1.x * sa;
        const float o2b = x2.y * cb + x1.y * sb;
        const size_t wb = (size_t)s * KW + h * DKW;
        uint32_t H, L;
        packpair(o1a, o1b, H, L);
        qH[wb + j] = H;      qL[wb + j] = L;
        packpair(o2a, o2b, H, L);
        qH[wb + 64 + j] = H; qL[wb + 64 + j] = L;
    }
    {
        const float* base = k + (size_t)s * DHD;
        float2 x1 = *(const float2*)&base[2 * j];
        float2 x2 = *(const float2*)&base[128 + 2 * j];
        const float o1a = x1.x * ca - x2.x * sa;
        const float o1b = x1.y * cb - x2.y * sb;
        const float o2a = x2.x * ca + x1.x * sa;
        const float o2b = x2.y * cb + x1.y * sb;
        const size_t wb = (size_t)s * DKW;
        uint32_t H, L;
        packpair(o1a, o1b, H, L);
        kH[wb + j] = H;      kL[wb + j] = L;
        packpair(o2a, o2b, H, L);
        kH[wb + 64 + j] = H; kL[wb + 64 + j] = L;
    }
}

// ---------------------------------------------------------------------------
// GEMM on pre-split inputs: C[M,N] = A @ Bt^T (logical fp32 via 3-term bf16).
// A,B given as packed hi/lo u32 [rows][Kw]. CTA 128x128, 8 warps, chunk 16 words.
// cp.async double-buffered; ldmatrix fragments; term-major mma order.
// smem pitch 20 words/row; per buffer 4 arrays x 128 x 20 = 10240 words.
// ---------------------------------------------------------------------------
#define GP 20
#define OAL_B 10240      // bytes: 2560 words
#define OBH_B 20480
#define OBL_B 30720
#define BUFW  10240      // words per buffer
#define GEMM_SMEM (2 * BUFW * 4)   // 81920 B

__global__ __launch_bounds__(256, 1)
void gemm_presplit(const uint32_t* __restrict__ AH, const uint32_t* __restrict__ AL,
                   const uint32_t* __restrict__ BH, const uint32_t* __restrict__ BL,
                   float* __restrict__ C, int M, int N, int Kw)
{
    extern __shared__ uint32_t smu[];
    const uint32_t sb = smem_u32(smu);

    const int tid  = threadIdx.x;
    const int wid  = tid >> 5, lane = tid & 31;
    const int g    = lane >> 2, tig = lane & 3;
    const int l8   = lane & 7, lb3 = (lane >> 3) & 1, lb4 = (lane >> 4) & 1;
    const int wm   = (wid & 1) * 64;
    const int wn   = (wid >> 1) * 32;
    const int m0   = blockIdx.y * 128, n0 = blockIdx.x * 128;

    const int lr = tid >> 1;               // 0..127
    const int wc = (tid & 1) * 8;          // word col 0 or 8
    const uint32_t* gah = AH + (size_t)(m0 + lr) * Kw + wc;
    const uint32_t* gal = AL + (size_t)(m0 + lr) * Kw + wc;
    const uint32_t* gbh = BH + (size_t)(n0 + lr) * Kw + wc;
    const uint32_t* gbl = BL + (size_t)(n0 + lr) * Kw + wc;

#define GISSUE(ci, bufbyte) do {                                            \
        const uint32_t _b = sb + (bufbyte) + (lr * GP + wc) * 4;            \
        const uint32_t* _g;                                                 \
        _g = gah + (ci) * 16; CP16(_b,             _g); CP16(_b + 16,          _g + 4); \
        _g = gal + (ci) * 16; CP16(_b + OAL_B,     _g); CP16(_b + OAL_B + 16,  _g + 4); \
        _g = gbh + (ci) * 16; CP16(_b + OBH_B,     _g); CP16(_b + OBH_B + 16,  _g + 4); \
        _g = gbl + (ci) * 16; CP16(_b + OBL_B,     _g); CP16(_b + OBL_B + 16,  _g + 4); \
    } while (0)

    float c[16][4];
    #pragma unroll
    for (int i = 0; i < 16; ++i)
        #pragma unroll
        for (int j = 0; j < 4; ++j) c[i][j] = 0.f;

    const int nch = Kw / 16;
    GISSUE(0, 0);
    CPCOMMIT();

    for (int c0 = 0; c0 < nch; ++c0) {
        const uint32_t cb = (uint32_t)(c0 & 1) * (BUFW * 4);
        if (c0 + 1 < nch) {
            GISSUE(c0 + 1, (uint32_t)((c0 + 1) & 1) * (BUFW * 4));
            CPCOMMIT();
            CPWAIT1();
        } else {
            CPWAIT0();
        }
        __syncthreads();

        #pragma unroll
        for (int ks = 0; ks < 2; ++ks) {
            const int wb = ks * 8;
            uint32_t aH[4][4], aL[4][4], bH[2][4], bL[2][4];
            #pragma unroll
            for (int mt = 0; mt < 4; ++mt) {
                const uint32_t ro = (uint32_t)((wm + mt * 16 + l8 + lb3 * 8) * GP
                                               + wb + lb4 * 4) * 4;
                ldsm_x4(aH[mt], sb + cb + ro);
                ldsm_x4(aL[mt], sb + cb + OAL_B + ro);
            }
            #pragma unroll
            for (int p = 0; p < 2; ++p) {
                const uint32_t ro = (uint32_t)((wn + p * 16 + lb4 * 8 + l8) * GP
                                               + wb + lb3 * 4) * 4;
                ldsm_x4(bH[p], sb + cb + OBH_B + ro);
                ldsm_x4(bL[p], sb + cb + OBL_B + ro);
            }
            // term-major: hi*hi, hi*lo, lo*hi (acc reuse distance 16)
            #pragma unroll
            for (int mt = 0; mt < 4; ++mt)
                #pragma unroll
                for (int nt = 0; nt < 4; ++nt)
                    MMA_BF16(c[mt * 4 + nt], aH[mt], &bH[nt >> 1][(nt & 1) * 2]);
            #pragma unroll
            for (int mt = 0; mt < 4; ++mt)
                #pragma unroll
                for (int nt = 0; nt < 4; ++nt)
                    MMA_BF16(c[mt * 4 + nt], aH[mt], &bL[nt >> 1][(nt & 1) * 2]);
            #pragma unroll
            for (int mt = 0; mt < 4; ++mt)
                #pragma unroll
                for (int nt = 0; nt < 4; ++nt)
                    MMA_BF16(c[mt * 4 + nt], aL[mt], &bH[nt >> 1][(nt & 1) * 2]);
        }
        __syncthreads();
    }
#undef GISSUE

    #pragma unroll
    for (int mt = 0; mt < 4; ++mt)
        #pragma unroll
        for (int nt = 0; nt < 4; ++nt) {
            const float* cc = c[mt * 4 + nt];
            const int row = m0 + wm + mt * 16 + g;
            const int col = n0 + wn + nt * 8 + 2 * tig;
            *(float2*)&C[(size_t)row * N + col]       = make_float2(cc[0], cc[1]);
            *(float2*)&C[(size_t)(row + 8) * N + col] = make_float2(cc[2], cc[3]);
        }
}

// ---------------------------------------------------------------------------
// Flash attention: pre-split Q/K from gmem; V transposed+packed in-kernel;
// ldmatrix fragments; term-major mma; writes packed attn hi/lo.
// ---------------------------------------------------------------------------
#define QP 132
#define VP 36
#define PP 68
#define OFF_QH 0
#define OFF_QL (OFF_QH + 64 * QP)
#define OFF_KH (OFF_QL + 64 * QP)
#define OFF_KL (OFF_KH + 64 * QP)
#define OFF_VTH (OFF_KL + 64 * QP)
#define OFF_VTL (OFF_VTH + 256 * VP)
#define OFF_PS  (OFF_VTL + 256 * VP)
#define OFF_M   (OFF_PS + 64 * PP)
#define OFF_L   (OFF_M + 64)
#define OFF_C   (OFF_L + 64)
#define FA3_SMEM ((OFF_C + 64) * 4)

__global__ __launch_bounds__(256, 1) void flash_mma_bf16(
    const uint32_t* __restrict__ Qh, const uint32_t* __restrict__ Ql,
    const uint32_t* __restrict__ Kh, const uint32_t* __restrict__ Kl,
    const float* __restrict__ Vg,
    uint32_t* __restrict__ AHo, uint32_t* __restrict__ ALo)
{
    extern __shared__ uint32_t smu[];
    float* smf = (float*)smu;
    const uint32_t sb = smem_u32(smu);

    const int tid  = threadIdx.x;
    const int wid  = tid >> 5, lane = tid & 31;
    const int g    = lane >> 2, tig = lane & 3;
    const int l8   = lane & 7, lb3 = (lane >> 3) & 1, lb4 = (lane >> 4) & 1;
    const int h    = blockIdx.y;
    const int it   = gridDim.x - 1 - blockIdx.x;

    const int wqm = (wid & 1) * 32;        // QK^T: 2 M-groups x 4 N-groups
    const int wqn = (wid >> 1) * 16;
    const int wpm = (wid & 3) * 16;        // P*V: 4 M-groups x 2 N-groups
    const int wpn = (wid >> 2) * 128;

    const int lr = tid & 63, lq = (tid >> 6) * 32;   // loader: row, 32-word seg
    const int vrp = tid >> 3, vin = tid & 7;          // V loader
    const int srow = tid >> 2, sseg = tig * 16;       // softmax

    // ---- stage Q (copy pre-split words) + init state ----
    {
        const uint32_t* sH = Qh + (size_t)(it * 64 + lr) * KW + h * DKW + lq;
        const uint32_t* sL = Ql + (size_t)(it * 64 + lr) * KW + h * DKW + lq;
        const int d = lr * QP + lq;
        #pragma unroll
        for (int i = 0; i < 8; ++i) {
            *(uint4*)&smu[OFF_QH + d + 4 * i] = *(const uint4*)(sH + 4 * i);
            *(uint4*)&smu[OFF_QL + d + 4 * i] = *(const uint4*)(sL + 4 * i);
        }
        if (tid < 64) { smf[OFF_M + tid] = -1e30f; smf[OFF_L + tid] = 0.f; }
    }

    float o[16][4];
    #pragma unroll
    for (int i = 0; i < 16; ++i)
        #pragma unroll
        for (int j = 0; j < 4; ++j) o[i][j] = 0.f;

    const int rowq0 = wqm + l8 + lb3 * 8;
    const int rowk  = wqn + lb4 * 8 + l8;
    const int rowp  = wpm + l8 + lb3 * 8;

    for (int jt = 0; jt <= it; ++jt) {
        __syncthreads();

        // ---- stage K (copy) ----
        {
            const uint32_t* sH = Kh + (size_t)(jt * 64 + lr) * DKW + lq;
            const uint32_t* sL = Kl + (size_t)(jt * 64 + lr) * DKW + lq;
            const int d = lr * QP + lq;
            #pragma unroll
            for (int i = 0; i < 8; ++i) {
                *(uint4*)&smu[OFF_KH + d + 4 * i] = *(const uint4*)(sH + 4 * i);
                *(uint4*)&smu[OFF_KL + d + 4 * i] = *(const uint4*)(sL + 4 * i);
            }
        }
        // ---- stage V transposed+packed ----
        {
            const float* V0 = Vg + (size_t)(jt * 64 + 2 * vrp) * DHD;
            const float* V1 = V0 + DHD;
            #pragma unroll
            for (int i = 0; i < 8; ++i) {
                const int d = i * 32 + vin * 4;
                float4 a = *(const float4*)(V0 + d);
                float4 b = *(const float4*)(V1 + d);
                const float av[4] = {a.x, a.y, a.z, a.w};
                const float bv[4] = {b.x, b.y, b.z, b.w};
                #pragma unroll
                for (int j = 0; j < 4; ++j) {
                    uint32_t H, L;
                    packpair(av[j], bv[j], H, L);
                    smu[OFF_VTH + (d + j) * VP + vrp] = H;
                    smu[OFF_VTL + (d + j) * VP + vrp] = L;
                }
            }
        }
        __syncthreads();

        // ---- Phase A: S = Q K^T  (16 k-steps of 16) ----
        {
            float s[2][2][4];
            #pragma unroll
            for (int a = 0; a < 2; ++a)
                #pragma unroll
                for (int b = 0; b < 2; ++b)
                    #pragma unroll
                    for (int j = 0; j < 4; ++j) s[a][b][j] = 0.f;

            #pragma unroll 4
            for (int ks = 0; ks < 16; ++ks) {
                const int wb = ks * 8;
                uint32_t aH0[4], aH1[4], aL0[4], aL1[4], bH[4], bL[4];
                const uint32_t qo = (uint32_t)(rowq0 * QP + wb + lb4 * 4) * 4;
                ldsm_x4(aH0, sb + OFF_QH * 4 + qo);
                ldsm_x4(aH1, sb + OFF_QH * 4 + qo + 16 * QP * 4);
                ldsm_x4(aL0, sb + OFF_QL * 4 + qo);
                ldsm_x4(aL1, sb + OFF_QL * 4 + qo + 16 * QP * 4);
                const uint32_t ko = (uint32_t)(rowk * QP + wb + lb3 * 4) * 4;
                ldsm_x4(bH, sb + OFF_KH * 4 + ko);
                ldsm_x4(bL, sb + OFF_KL * 4 + ko);
                // term-major
                MMA_BF16(s[0][0], aH0, &bH[0]); MMA_BF16(s[0][1], aH0, &bH[2]);
                MMA_BF16(s[1][0], aH1, &bH[0]); MMA_BF16(s[1][1], aH1, &bH[2]);
                MMA_BF16(s[0][0], aH0, &bL[0]); MMA_BF16(s[0][1], aH0, &bL[2]);
                MMA_BF16(s[1][0], aH1, &bL[0]); MMA_BF16(s[1][1], aH1, &bL[2]);
                MMA_BF16(s[0][0], aL0, &bH[0]); MMA_BF16(s[0][1], aL0, &bH[2]);
                MMA_BF16(s[1][0], aL1, &bH[0]); MMA_BF16(s[1][1], aL1, &bH[2]);
            }
            #pragma unroll
            for (int mf = 0; mf < 2; ++mf)
                #pragma unroll
                for (int nf = 0; nf < 2; ++nf) {
                    const int row = wqm + mf * 16 + g;
                    const int col = wqn + nf * 8 + 2 * tig;
                    *(float2*)&smf[OFF_PS + row * PP + col] =
                        make_float2(s[mf][nf][0], s[mf][nf][1]);
                    *(float2*)&smf[OFF_PS + (row + 8) * PP + col] =
                        make_float2(s[mf][nf][2], s[mf][nf][3]);
                }
        }
        __syncthreads();

        // ---- Phase B: online softmax; pack P in-place (Ph w0-31, Pl w32-63) ----
        {
            const bool diag = (jt == it);
            float pv[16];
            float mx = -1e30f;
            #pragma unroll
            for (int c = 0; c < 16; ++c) {
                const int col = sseg + c;
                float val = smf[OFF_PS + srow * PP + col] * 0.0625f;
                if (diag && col > srow) val = -1e30f;
                pv[c] = val;
                mx = fmaxf(mx, val);
            }
            mx = fmaxf(mx, __shfl_xor_sync(0xffffffffu, mx, 1));
            mx = fmaxf(mx, __shfl_xor_sync(0xffffffffu, mx, 2));
            const float m_old = smf[OFF_M + srow];
            const float m_new = fmaxf(m_old, mx);
            const float corr  = __expf(m_old - m_new);
            float lsum = 0.f;
            #pragma unroll
            for (int c = 0; c < 16; ++c) {
                pv[c] = __expf(pv[c] - m_new);
                lsum += pv[c];
            }
            lsum += __shfl_xor_sync(0xffffffffu, lsum, 1);
            lsum += __shfl_xor_sync(0xffffffffu, lsum, 2);
            if (tig == 0) {
                smf[OFF_M + srow] = m_new;
                smf[OFF_L + srow] = smf[OFF_L + srow] * corr + lsum;
                smf[OFF_C + srow] = corr;
            }
            __syncwarp();
            const int wbse = OFF_PS + srow * PP + tig * 8;
            #pragma unroll
            for (int i = 0; i < 8; ++i) {
                uint32_t H, L;
                packpair(pv[2 * i], pv[2 * i + 1], H, L);
                smu[wbse + i]      = H;
                smu[wbse + 32 + i] = L;
            }
        }
        __syncthreads();

        // ---- Phase C: acc = acc*corr + P @ V  (4 k-steps of 16) ----
        {
            const float c_lo = smf[OFF_C + wpm + g];
            const float c_hi = smf[OFF_C + wpm + g + 8];
            #pragma unroll
            for (int nf = 0; nf < 16; ++nf) {
                o[nf][0] *= c_lo; o[nf][1] *= c_lo;
                o[nf][2] *= c_hi; o[nf][3] *= c_hi;
            }
            #pragma unroll
            for (int ks = 0; ks < 4; ++ks) {
                const int wb = ks * 8;
                uint32_t pH[4], pL[4];
                const uint32_t po = (uint32_t)(rowp * PP + wb + lb4 * 4) * 4;
                ldsm_x4(pH, sb + OFF_PS * 4 + po);
                ldsm_x4(pL, sb + OFF_PS * 4 + po + 128);
                #pragma unroll
                for (int grp = 0; grp < 16; grp += 8) {
                    uint32_t vH[4][4], vL[4][4];
                    #pragma unroll
                    for (int qd = 0; qd < 4; ++qd) {
                        const uint32_t vo = (uint32_t)(
                            (wpn + (grp + 2 * qd) * 8 + lb4 * 8 + l8) * VP
                            + wb + lb3 * 4) * 4;
                        ldsm_x4(vH[qd], sb + OFF_VTH * 4 + vo);
                        ldsm_x4(vL[qd], sb + OFF_VTL * 4 + vo);
                    }
                    #pragma unroll
                    for (int qd = 0; qd < 4; ++qd) {
                        MMA_BF16(o[grp + 2 * qd],     pH, &vH[qd][0]);
                        MMA_BF16(o[grp + 2 * qd + 1], pH, &vH[qd][2]);
                    }
                    #pragma unroll
                    for (int qd = 0; qd < 4; ++qd) {
                        MMA_BF16(o[grp + 2 * qd],     pH, &vL[qd][0]);
                        MMA_BF16(o[grp + 2 * qd + 1], pH, &vL[qd][2]);
                    }
                    #pragma unroll
                    for (int qd = 0; qd < 4; ++qd) {
                        MMA_BF16(o[grp + 2 * qd],     pL, &vH[qd][0]);
                        MMA_BF16(o[grp + 2 * qd + 1], pL, &vH[qd][2]);
                    }
                }
            }
        }
    }

    // ---- normalize and write packed attn ----
    __syncthreads();
    {
        const float inv_lo = 1.0f / smf[OFF_L + wpm + g];
        const float inv_hi = 1.0f / smf[OFF_L + wpm + g + 8];
        const size_t row_lo = (size_t)(it * 64 + wpm + g);
        const size_t row_hi = row_lo + 8;
        #pragma unroll
        for (int nf = 0; nf < 16; ++nf) {
            const int wcol = h * DKW + (wpn >> 1) + nf * 4 + tig;
            uint32_t H, L;
            packpair(o[nf][0] * inv_lo, o[nf][1] * inv_lo, H, L);
            AHo[row_lo * KW + wcol] = H;
            ALo[row_lo * KW + wcol] = L;
            packpair(o[nf][2] * inv_hi, o[nf][3] * inv_hi, H, L);
            AHo[row_hi * KW + wcol] = H;
            ALo[row_hi * KW + wcol] = L;
        }
    }
}

// ---------------------------------------------------------------------------
extern "C" void kernel_launch(void* const* d_in, const int* in_sizes, int n_in,
                              void* d_out, int out_size)
{
    const float* X   = (const float*)d_in[0];
    const int*   pos = (const int*)  d_in[1];
    const float* wq  = (const float*)d_in[2];
    const float* wk  = (const float*)d_in[3];
    const float* wv  = (const float*)d_in[4];
    const float* wo  = (const float*)d_in[5];
    float* out = (float*)d_out;

    float *q, *k, *v;
    uint32_t *xH, *xL, *qH, *qL, *kH, *kL, *aH, *aL;
    uint32_t *wqH, *wqL, *wkH, *wkL, *wvH, *wvL, *woH, *woL;
    cudaGetSymbolAddress((void**)&q,   g_q);
    cudaGetSymbolAddress((void**)&k,   g_k);
    cudaGetSymbolAddress((void**)&v,   g_v);
    cudaGetSymbolAddress((void**)&xH,  g_xH);  cudaGetSymbolAddress((void**)&xL,  g_xL);
    cudaGetSymbolAddress((void**)&qH,  g_qH);  cudaGetSymbolAddress((void**)&qL,  g_qL);
    cudaGetSymbolAddress((void**)&kH,  g_kH);  cudaGetSymbolAddress((void**)&kL,  g_kL);
    cudaGetSymbolAddress((void**)&aH,  g_aH);  cudaGetSymbolAddress((void**)&aL,  g_aL);
    cudaGetSymbolAddress((void**)&wqH, g_wqH); cudaGetSymbolAddress((void**)&wqL, g_wqL);
    cudaGetSymbolAddress((void**)&wkH, g_wkH); cudaGetSymbolAddress((void**)&wkL, g_wkL);
    cudaGetSymbolAddress((void**)&wvH, g_wvH); cudaGetSymbolAddress((void**)&wvL, g_wvL);
    cudaGetSymbolAddress((void**)&woH, g_woH); cudaGetSymbolAddress((void**)&woL, g_woL);

    // pre-split inputs
    split_rows<<<S_LEN * KW / (256 * 4), 256>>>(X, xH, xL);
    dim3 tb(32, 8);
    transpose_split<<<dim3(HID / 32, HID / 32), tb>>>(wq, wqH, wqL, HID, HID);
    transpose_split<<<dim3(DHD / 32, HID / 32), tb>>>(wk, wkH, wkL, HID, DHD);
    transpose_split<<<dim3(DHD / 32, HID / 32), tb>>>(wv, wvH, wvL, HID, DHD);
    transpose_split<<<dim3(HID / 32, HID / 32), tb>>>(wo, woH, woL, HID, HID);

    cudaFuncSetAttribute(gemm_presplit,
                         cudaFuncAttributeMaxDynamicSharedMemorySize, GEMM_SMEM);

    gemm_presplit<<<dim3(HID / 128, S_LEN / 128), 256, GEMM_SMEM>>>(
        xH, xL, wqH, wqL, q, S_LEN, HID, KW);
    gemm_presplit<<<dim3(DHD / 128, S_LEN / 128), 256, GEMM_SMEM>>>(
        xH, xL, wkH, wkL, k, S_LEN, DHD, KW);
    gemm_presplit<<<dim3(DHD / 128, S_LEN / 128), 256, GEMM_SMEM>>>(
        xH, xL, wvH, wvL, v, S_LEN, DHD, KW);

    rope_split<<<S_LEN, 64>>>(q, k, pos, qH, qL, kH, kL);

    cudaFuncSetAttribute(flash_mma_bf16,
                         cudaFuncAttributeMaxDynamicSharedMemorySize, FA3_SMEM);
    flash_mma_bf16<<<dim3(S_LEN / 64, NH), 256, FA3_SMEM>>>(
        qH, qL, kH, kL, v, aH, aL);

    gemm_presplit<<<dim3(HID / 128, S_LEN / 128), 256, GEMM_SMEM>>>(
        aH, aL, woH, woL, out, S_LEN, HID, KW);
}